// round 5
// baseline (speedup 1.0000x reference)
#include <cuda_runtime.h>
#include <cuda_bf16.h>
#include <cstdint>
#include <cstddef>

#define N_NODES 100000
#define N_EDGES 600000
#define HD 128
#define TILE_M 128
#define SCAN_CHUNK 1024
#define NBLK ((N_NODES + SCAN_CHUNK - 1) / SCAN_CHUNK)   // 98

// ---- scratch (allocation-free) ----
__device__ float g_M[(size_t)N_NODES * HD];
__device__ float g_H[(size_t)N_NODES * HD];
__device__ int   g_deg[N_NODES];
__device__ int   g_rowptr[N_NODES];
__device__ int   g_cursor[N_NODES];
__device__ int   g_ssrc[N_EDGES];
__device__ int   g_partials[NBLK];
__device__ __nv_bfloat16 g_WT_hi[HD * HD];   // WT[n][k] = W[k][n], hi split
__device__ __nv_bfloat16 g_WT_lo[HD * HD];   // residual split

__device__ __forceinline__ float leaky(float x) { return x > 0.f ? x : 0.2f * x; }

// pack two f32 -> bf16x2: lo_half holds first arg, hi_half second
__device__ __forceinline__ uint32_t cvt_bf2(float lo_half, float hi_half) {
    uint32_t r;
    asm("cvt.rn.bf16x2.f32 %0, %1, %2;" : "=r"(r) : "f"(hi_half), "f"(lo_half));
    return r;
}

// D += A * B  (m16n8k16, bf16 in, f32 accum) — plain sm_80+ PTX, no 'a' features
__device__ __forceinline__ void mma16816(float* d, const uint32_t* a, uint32_t b0, uint32_t b1) {
    asm volatile(
        "mma.sync.aligned.m16n8k16.row.col.f32.bf16.bf16.f32 "
        "{%0,%1,%2,%3}, {%4,%5,%6,%7}, {%8,%9}, {%0,%1,%2,%3};"
        : "+f"(d[0]), "+f"(d[1]), "+f"(d[2]), "+f"(d[3])
        : "r"(a[0]), "r"(a[1]), "r"(a[2]), "r"(a[3]), "r"(b0), "r"(b1));
}

// ================= W^T hi/lo prep =================
__global__ void prep_wt_kernel(const float* __restrict__ W,
                               __nv_bfloat16* __restrict__ wt_hi,
                               __nv_bfloat16* __restrict__ wt_lo) {
    int idx = blockIdx.x * 256 + threadIdx.x;
    if (idx >= HD * HD) return;
    int n = idx >> 7, k = idx & 127;
    float x = W[k * HD + n];
    __nv_bfloat16 h = __float2bfloat16_rn(x);
    float r = x - __bfloat162float(h);
    wt_hi[idx] = h;
    wt_lo[idx] = __float2bfloat16_rn(r);
}

// ================= HMMA GEMM =================
// out[row,:] = (X[gather(row),:] @ W) * norm[row], split-bf16 3-product
// SMEM: As f32[128][128] (64KB) + Bhi bf16[128][128] (32KB) + Blo (32KB) = 128KB
#define SM_AS  0
#define SM_BHI 65536
#define SM_BLO 98304
#define SM_TOTAL 131072

__global__ __launch_bounds__(512, 1)
void hmma_gemm_kernel(const float* __restrict__ X,
                      const int* __restrict__ idx,    // nullable
                      const __nv_bfloat16* __restrict__ wt_hi,
                      const __nv_bfloat16* __restrict__ wt_lo,
                      const float* __restrict__ norm,
                      float* __restrict__ out) {
    extern __shared__ char smem[];
    float* As = reinterpret_cast<float*>(smem + SM_AS);
    const int t = threadIdx.x;
    const int row0 = blockIdx.x * TILE_M;

    // ---- stage A (f32, XOR-swizzled float2 granules) ----
    {
        const int r = t >> 2;              // 0..127
        const int row = row0 + r;
        const uint32_t m = (r & 7) << 2;   // swizzle mask on float2-granule index
        if (row < N_NODES) {
            const int srow = idx ? __ldg(idx + row) : row;
            const float4* sr = reinterpret_cast<const float4*>(X + (size_t)srow * HD);
            #pragma unroll
            for (int j = 0; j < 8; ++j) {
                int c4 = (t & 3) * 8 + j;              // float4 col index 0..31
                float4 v = __ldg(sr + c4);
                uint32_t gq = (uint32_t)(2 * c4) ^ m;  // swizzled float2 granule
                *reinterpret_cast<float4*>(As + r * 128 + gq * 2) = v;
            }
        } else {
            #pragma unroll
            for (int j = 0; j < 8; ++j) {
                int c4 = (t & 3) * 8 + j;
                uint32_t gq = (uint32_t)(2 * c4) ^ m;
                *reinterpret_cast<float4*>(As + r * 128 + gq * 2) =
                    make_float4(0.f, 0.f, 0.f, 0.f);
            }
        }
    }
    // ---- stage B hi/lo (bf16, XOR-swizzled u32 granules) ----
    {
        const int r = t >> 2;              // B row = n, 0..127
        const uint32_t m = (r & 7) << 2;
        const uint4* bh = reinterpret_cast<const uint4*>(wt_hi + r * HD);
        const uint4* bl = reinterpret_cast<const uint4*>(wt_lo + r * HD);
        #pragma unroll
        for (int j = 0; j < 4; ++j) {
            int u = (t & 3) * 4 + j;                    // uint4 index 0..15
            uint32_t q = (uint32_t)(4 * u) ^ m;         // swizzled u32 granule
            *reinterpret_cast<uint4*>(smem + SM_BHI + r * 256 + q * 4) = __ldg(bh + u);
            *reinterpret_cast<uint4*>(smem + SM_BLO + r * 256 + q * 4) = __ldg(bl + u);
        }
    }
    __syncthreads();

    // ---- warp tiling: 16 warps = 4 row-groups x 4 col-groups; warp tile 32x32 ----
    const int lane = t & 31, wid = t >> 5;
    const int wr = wid >> 2, wc = wid & 3;
    const int g = lane >> 2, tq = lane & 3;
    const uint32_t mg = (uint32_t)(g << 2);  // all fragment rows have (row&7)==g

    float acc[2][4][4];
    #pragma unroll
    for (int mt = 0; mt < 2; ++mt)
        #pragma unroll
        for (int nt = 0; nt < 4; ++nt)
            #pragma unroll
            for (int c = 0; c < 4; ++c) acc[mt][nt][c] = 0.f;

    #pragma unroll
    for (int s = 0; s < 8; ++s) {
        const uint32_t p0 = ((uint32_t)(8 * s + tq)) ^ mg;      // k-low granule
        const uint32_t p1 = ((uint32_t)(8 * s + tq + 4)) ^ mg;  // k-high granule

        // A fragments (2 m16 tiles), converted to hi/lo bf16x2 in registers
        uint32_t ahi[2][4], alo[2][4];
        #pragma unroll
        for (int mt = 0; mt < 2; ++mt) {
            const int ra = wr * 32 + mt * 16 + g;
            const float* Ra = As + ra * 128;
            const float* Rb = As + (ra + 8) * 128;
            float2 f0 = *reinterpret_cast<const float2*>(Ra + p0 * 2);
            float2 f1 = *reinterpret_cast<const float2*>(Rb + p0 * 2);
            float2 f2 = *reinterpret_cast<const float2*>(Ra + p1 * 2);
            float2 f3 = *reinterpret_cast<const float2*>(Rb + p1 * 2);
            uint32_t h0 = cvt_bf2(f0.x, f0.y);
            uint32_t h1 = cvt_bf2(f1.x, f1.y);
            uint32_t h2 = cvt_bf2(f2.x, f2.y);
            uint32_t h3 = cvt_bf2(f3.x, f3.y);
            ahi[mt][0] = h0; ahi[mt][1] = h1; ahi[mt][2] = h2; ahi[mt][3] = h3;
            alo[mt][0] = cvt_bf2(f0.x - __uint_as_float(h0 << 16),
                                 f0.y - __uint_as_float(h0 & 0xFFFF0000u));
            alo[mt][1] = cvt_bf2(f1.x - __uint_as_float(h1 << 16),
                                 f1.y - __uint_as_float(h1 & 0xFFFF0000u));
            alo[mt][2] = cvt_bf2(f2.x - __uint_as_float(h2 << 16),
                                 f2.y - __uint_as_float(h2 & 0xFFFF0000u));
            alo[mt][3] = cvt_bf2(f3.x - __uint_as_float(h3 << 16),
                                 f3.y - __uint_as_float(h3 & 0xFFFF0000u));
        }

        // B fragments (4 n8 tiles) + 3-product MMAs
        #pragma unroll
        for (int nt = 0; nt < 4; ++nt) {
            const int rb = wc * 32 + nt * 8 + g;
            const uint32_t* BH = reinterpret_cast<const uint32_t*>(smem + SM_BHI + rb * 256);
            const uint32_t* BL = reinterpret_cast<const uint32_t*>(smem + SM_BLO + rb * 256);
            uint32_t bh0 = BH[p0], bh1 = BH[p1];
            uint32_t bl0 = BL[p0], bl1 = BL[p1];
            #pragma unroll
            for (int mt = 0; mt < 2; ++mt) {
                mma16816(acc[mt][nt], ahi[mt], bh0, bh1);
                mma16816(acc[mt][nt], ahi[mt], bl0, bl1);
                mma16816(acc[mt][nt], alo[mt], bh0, bh1);
            }
        }
    }

    // ---- epilogue: scale by norm, store f32 ----
    #pragma unroll
    for (int mt = 0; mt < 2; ++mt) {
        const int rA = row0 + wr * 32 + mt * 16 + g;
        const int rB = rA + 8;
        const bool okA = rA < N_NODES, okB = rB < N_NODES;
        const float sA = okA ? __ldg(norm + rA) : 0.f;
        const float sB = okB ? __ldg(norm + rB) : 0.f;
        #pragma unroll
        for (int nt = 0; nt < 4; ++nt) {
            const int col = wc * 32 + nt * 8 + tq * 2;
            if (okA) {
                float2 v = make_float2(acc[mt][nt][0] * sA, acc[mt][nt][1] * sA);
                *reinterpret_cast<float2*>(out + (size_t)rA * HD + col) = v;
            }
            if (okB) {
                float2 v = make_float2(acc[mt][nt][2] * sB, acc[mt][nt][3] * sB);
                *reinterpret_cast<float2*>(out + (size_t)rB * HD + col) = v;
            }
        }
    }
}

// ================= CSR build =================

__global__ void hist_kernel(const int* __restrict__ dst, int* __restrict__ deg) {
    int e = blockIdx.x * 256 + threadIdx.x;
    if (e < N_EDGES) atomicAdd(&deg[dst[e]], 1);
}

__global__ void scan_block_kernel(const int* __restrict__ deg,
                                  int* __restrict__ rowptr,
                                  int* __restrict__ partials) {
    __shared__ int wsum[8];
    const int t = threadIdx.x;
    const int base = blockIdx.x * SCAN_CHUNK + t * 4;
    int v[4];
    #pragma unroll
    for (int j = 0; j < 4; ++j) {
        int i = base + j;
        v[j] = (i < N_NODES) ? deg[i] : 0;
    }
    int s = v[0] + v[1] + v[2] + v[3];
    const int lane = t & 31, wid = t >> 5;
    int x = s;
    #pragma unroll
    for (int o = 1; o < 32; o <<= 1) {
        int y = __shfl_up_sync(~0u, x, o);
        if (lane >= o) x += y;
    }
    if (lane == 31) wsum[wid] = x;
    __syncthreads();
    if (wid == 0) {
        int ws = (lane < 8) ? wsum[lane] : 0;
        #pragma unroll
        for (int o = 1; o < 8; o <<= 1) {
            int y = __shfl_up_sync(~0u, ws, o);
            if (lane >= o) ws += y;
        }
        if (lane < 8) wsum[lane] = ws;
    }
    __syncthreads();
    int run = (x - s) + (wid > 0 ? wsum[wid - 1] : 0);
    #pragma unroll
    for (int j = 0; j < 4; ++j) {
        int i = base + j;
        if (i < N_NODES) rowptr[i] = run;
        run += v[j];
    }
    if (t == 0) partials[blockIdx.x] = wsum[7];
}

__global__ void scan_partials_kernel(int* __restrict__ partials) {
    __shared__ int wsum[4];
    const int t = threadIdx.x;
    int v = (t < NBLK) ? partials[t] : 0;
    const int lane = t & 31, wid = t >> 5;
    int x = v;
    #pragma unroll
    for (int o = 1; o < 32; o <<= 1) {
        int y = __shfl_up_sync(~0u, x, o);
        if (lane >= o) x += y;
    }
    if (lane == 31) wsum[wid] = x;
    __syncthreads();
    if (t == 0) {
        int a = 0;
        #pragma unroll
        for (int w = 0; w < 4; ++w) { int s2 = wsum[w]; wsum[w] = a; a += s2; }
    }
    __syncthreads();
    int excl = (x - v) + wsum[wid];
    if (t < NBLK) partials[t] = excl;
}

__global__ void scan_add_kernel(int* __restrict__ rowptr,
                                const int* __restrict__ partials,
                                int* __restrict__ cursor) {
    int i = blockIdx.x * 256 + threadIdx.x;
    if (i < N_NODES) {
        int r = rowptr[i] + partials[i >> 10];
        rowptr[i] = r;
        cursor[i] = r;
    }
}

__global__ void permute_kernel(const int* __restrict__ src,
                               const int* __restrict__ dst,
                               int* __restrict__ cursor,
                               int* __restrict__ ssrc) {
    int e = blockIdx.x * 256 + threadIdx.x;
    if (e < N_EDGES) {
        int d = dst[e];
        int pos = atomicAdd(&cursor[d], 1);
        ssrc[pos] = src[e];
    }
}

// ================= load-balanced gather + fused epilogue =================
// out[n,:] = leaky( (sum_{e: dst==n} M[src[e],:]) * norm[n] + b[:] )
#define GATHER_BLOCKS 512
__global__ void gather_kernel(const float* __restrict__ M,
                              const int* __restrict__ rowptr,
                              const int* __restrict__ deg,
                              const int* __restrict__ ssrc,
                              const float* __restrict__ norm,
                              const float* __restrict__ b,
                              float* __restrict__ out) {
    const int gw = blockIdx.x * 8 + (threadIdx.x >> 5);   // global warp id
    const int lane = threadIdx.x & 31;
    const int nwarps = GATHER_BLOCKS * 8;                  // 4096
    const float4 bb = __ldg(reinterpret_cast<const float4*>(b) + lane);

    for (int node = gw; node < N_NODES; node += nwarps) {
        const int start = __ldg(rowptr + node);
        const int d = __ldg(deg + node);
        float4 acc = make_float4(0.f, 0.f, 0.f, 0.f);
        #pragma unroll 4
        for (int j = 0; j < d; ++j) {
            int s = __ldg(ssrc + start + j);
            float4 v = __ldg(reinterpret_cast<const float4*>(M + (size_t)s * HD) + lane);
            acc.x += v.x; acc.y += v.y; acc.z += v.z; acc.w += v.w;
        }
        const float sc = __ldg(norm + node);
        float4 n;
        n.x = leaky(acc.x * sc + bb.x);
        n.y = leaky(acc.y * sc + bb.y);
        n.z = leaky(acc.z * sc + bb.z);
        n.w = leaky(acc.w * sc + bb.w);
        reinterpret_cast<float4*>(out + (size_t)node * HD)[lane] = n;
    }
}

extern "C" void kernel_launch(void* const* d_in, const int* in_sizes, int n_in,
                              void* d_out, int out_size) {
    const int*   node_id = (const int*)d_in[0];
    const int*   src     = (const int*)d_in[1];
    const int*   dst     = (const int*)d_in[2];
    const float* norm    = (const float*)d_in[3];
    const float* embed   = (const float*)d_in[4];
    const float* W1      = (const float*)d_in[5];
    const float* b1      = (const float*)d_in[6];
    const float* W2      = (const float*)d_in[7];
    const float* b2      = (const float*)d_in[8];
    float* out = (float*)d_out;

    void *pM, *pH, *pDeg, *pRow, *pCur, *pSS, *pPart, *pWh, *pWl;
    cudaGetSymbolAddress(&pM, g_M);
    cudaGetSymbolAddress(&pH, g_H);
    cudaGetSymbolAddress(&pDeg, g_deg);
    cudaGetSymbolAddress(&pRow, g_rowptr);
    cudaGetSymbolAddress(&pCur, g_cursor);
    cudaGetSymbolAddress(&pSS, g_ssrc);
    cudaGetSymbolAddress(&pPart, g_partials);
    cudaGetSymbolAddress(&pWh, g_WT_hi);
    cudaGetSymbolAddress(&pWl, g_WT_lo);
    float* M = (float*)pM;
    float* H = (float*)pH;
    int *deg = (int*)pDeg, *rowptr = (int*)pRow, *cursor = (int*)pCur;
    int *ssrc = (int*)pSS, *partials = (int*)pPart;
    __nv_bfloat16 *wt_hi = (__nv_bfloat16*)pWh, *wt_lo = (__nv_bfloat16*)pWl;

    cudaFuncSetAttribute(hmma_gemm_kernel,
                         cudaFuncAttributeMaxDynamicSharedMemorySize, SM_TOTAL);

    const int gemm_grid = (N_NODES + TILE_M - 1) / TILE_M;   // 782
    const int edge_grid = (N_EDGES + 255) / 256;
    const int node_grid = (N_NODES + 255) / 256;
    const int wt_grid   = (HD * HD + 255) / 256;

    // ---- CSR build ----
    cudaMemsetAsync(deg, 0, N_NODES * sizeof(int));
    hist_kernel<<<edge_grid, 256>>>(dst, deg);
    scan_block_kernel<<<NBLK, 256>>>(deg, rowptr, partials);
    scan_partials_kernel<<<1, 128>>>(partials);
    scan_add_kernel<<<node_grid, 256>>>(rowptr, partials, cursor);
    permute_kernel<<<edge_grid, 256>>>(src, dst, cursor, ssrc);

    // ---- Layer 1 ----
    prep_wt_kernel<<<wt_grid, 256>>>(W1, wt_hi, wt_lo);
    hmma_gemm_kernel<<<gemm_grid, 512, SM_TOTAL>>>(embed, node_id, wt_hi, wt_lo, norm, M);
    gather_kernel<<<GATHER_BLOCKS, 256>>>(M, rowptr, deg, ssrc, norm, b1, H);

    // ---- Layer 2 ----
    prep_wt_kernel<<<wt_grid, 256>>>(W2, wt_hi, wt_lo);
    hmma_gemm_kernel<<<gemm_grid, 512, SM_TOTAL>>>(H, nullptr, wt_hi, wt_lo, norm, M);
    gather_kernel<<<GATHER_BLOCKS, 256>>>(M, rowptr, deg, ssrc, norm, b2, out);
}

// round 6
// speedup vs baseline: 1.1306x; 1.1306x over previous
#include <cuda_runtime.h>
#include <cuda_bf16.h>
#include <cstdint>
#include <cstddef>

#define N_NODES 100000
#define N_EDGES 600000
#define HD 128
#define TILE_M 128
#define GTILES ((N_NODES + TILE_M - 1) / TILE_M)   // 782
#define GEMM_CTAS 148
#define SCAN_CHUNK 1024
#define NBLK ((N_NODES + SCAN_CHUNK - 1) / SCAN_CHUNK)   // 98

// ---- scratch (allocation-free) ----
__device__ float g_M[(size_t)N_NODES * HD];
__device__ float g_H[(size_t)N_NODES * HD];
__device__ int   g_deg[N_NODES];
__device__ int   g_rowptr[N_NODES];
__device__ int   g_cursor[N_NODES];
__device__ int   g_ssrc[N_EDGES];
__device__ int   g_partials[NBLK];
__device__ __nv_bfloat16 g_WT_hi[HD * HD];   // WT[n][k] = W[k][n], hi split
__device__ __nv_bfloat16 g_WT_lo[HD * HD];   // residual split

__device__ __forceinline__ float leaky(float x) { return x > 0.f ? x : 0.2f * x; }

__device__ __forceinline__ uint32_t smem_u32(const void* p) {
    uint32_t a;
    asm("{ .reg .u64 t; cvta.to.shared.u64 t, %1; cvt.u32.u64 %0, t; }" : "=r"(a) : "l"(p));
    return a;
}
// pack two f32 -> bf16x2: lo_half holds first arg
__device__ __forceinline__ uint32_t cvt_bf2(float lo_half, float hi_half) {
    uint32_t r;
    asm("cvt.rn.bf16x2.f32 %0, %1, %2;" : "=r"(r) : "f"(hi_half), "f"(lo_half));
    return r;
}
// D += A * B  (m16n8k16 bf16->f32) — plain sm_80 PTX
__device__ __forceinline__ void mma16816(float* d, const uint32_t* a, uint32_t b0, uint32_t b1) {
    asm volatile(
        "mma.sync.aligned.m16n8k16.row.col.f32.bf16.bf16.f32 "
        "{%0,%1,%2,%3}, {%4,%5,%6,%7}, {%8,%9}, {%0,%1,%2,%3};"
        : "+f"(d[0]), "+f"(d[1]), "+f"(d[2]), "+f"(d[3])
        : "r"(a[0]), "r"(a[1]), "r"(a[2]), "r"(a[3]), "r"(b0), "r"(b1));
}
__device__ __forceinline__ void cp_async16(uint32_t daddr, const void* gaddr, int src_bytes) {
    asm volatile("cp.async.cg.shared.global [%0], [%1], 16, %2;"
                 :: "r"(daddr), "l"(gaddr), "r"(src_bytes) : "memory");
}
#define CP_COMMIT() asm volatile("cp.async.commit_group;" ::: "memory")
#define CP_WAIT(n)  asm volatile("cp.async.wait_group %0;" :: "n"(n) : "memory")

// ================= W^T hi/lo prep =================
__global__ void prep_wt_kernel(const float* __restrict__ W,
                               __nv_bfloat16* __restrict__ wt_hi,
                               __nv_bfloat16* __restrict__ wt_lo) {
    int idx = blockIdx.x * 256 + threadIdx.x;
    if (idx >= HD * HD) return;
    int n = idx >> 7, k = idx & 127;
    float x = W[k * HD + n];
    __nv_bfloat16 h = __float2bfloat16_rn(x);
    float r = x - __bfloat162float(h);
    wt_hi[idx] = h;
    wt_lo[idx] = __float2bfloat16_rn(r);
}

// ================= persistent pipelined HMMA GEMM =================
// out[row,:] = (X[gather(row),:] @ W) * norm[row], split-bf16 3-product
// SMEM: Bhi 32KB | Blo 32KB | A-stage0 f32 64KB | A-stage1 f32 64KB = 192KB
#define SMB_BHI 0
#define SMB_BLO 32768
#define SMB_A0  65536
#define SMB_A1  131072
#define SM_TOTAL 196608

__global__ __launch_bounds__(512, 1)
void hmma_gemm_kernel(const float* __restrict__ X,
                      const int* __restrict__ idx,    // nullable
                      const __nv_bfloat16* __restrict__ wt_hi,
                      const __nv_bfloat16* __restrict__ wt_lo,
                      const float* __restrict__ norm,
                      float* __restrict__ out) {
    extern __shared__ char smem[];
    const uint32_t sb = smem_u32(smem);
    const int t = threadIdx.x;

    // ---- load B hi/lo once (XOR-swizzled u32 granules) ----
    {
        const int r = t >> 2;
        const uint32_t m = (r & 7) << 2;
        const uint4* bh = reinterpret_cast<const uint4*>(wt_hi + r * HD);
        const uint4* bl = reinterpret_cast<const uint4*>(wt_lo + r * HD);
        #pragma unroll
        for (int j = 0; j < 4; ++j) {
            int u = (t & 3) * 4 + j;
            uint32_t q = (uint32_t)(4 * u) ^ m;
            *reinterpret_cast<uint4*>(smem + SMB_BHI + r * 256 + q * 4) = __ldg(bh + u);
            *reinterpret_cast<uint4*>(smem + SMB_BLO + r * 256 + q * 4) = __ldg(bl + u);
        }
    }

    // tiles owned by this CTA
    int tiles[8];
    int ntl = 0;
    for (int tile = blockIdx.x; tile < GTILES; tile += GEMM_CTAS) tiles[ntl++] = tile;

    // stage A tile (f32, XOR-swizzled float2 granules) into buf via cp.async
    const int sr_ = t >> 2;                    // staged row 0..127
    const uint32_t sm_ = (sr_ & 7) << 2;
    auto stage = [&](int buf, int tile) {
        const int row = tile * TILE_M + sr_;
        const uint32_t abase = sb + (buf ? SMB_A1 : SMB_A0) + sr_ * 512;
        int srow = 0, vbytes = 0;
        if (row < N_NODES) { srow = idx ? __ldg(idx + row) : row; vbytes = 16; }
        const float4* g = reinterpret_cast<const float4*>(X + (size_t)srow * HD);
        #pragma unroll
        for (int j = 0; j < 8; ++j) {
            int c4 = (t & 3) * 8 + j;
            uint32_t gq = (uint32_t)(2 * c4) ^ sm_;
            cp_async16(abase + gq * 8, g + c4, vbytes);
        }
    };

    // warp tiling: 16 warps = 4x4; warp tile 32x32
    const int lane = t & 31, wid = t >> 5;
    const int wr = wid >> 2, wc = wid & 3;
    const int g = lane >> 2, tq = lane & 3;
    const uint32_t mg = (uint32_t)(g << 2);

    stage(0, tiles[0]);
    CP_COMMIT();

    for (int i = 0; i < ntl; ++i) {
        if (i + 1 < ntl) {
            stage((i + 1) & 1, tiles[i + 1]);
            CP_COMMIT();
            CP_WAIT(1);
        } else {
            CP_WAIT(0);
        }
        __syncthreads();

        const float* As = reinterpret_cast<const float*>(smem + ((i & 1) ? SMB_A1 : SMB_A0));
        const int row0 = tiles[i] * TILE_M;

        float acc[2][4][4];
        #pragma unroll
        for (int mt = 0; mt < 2; ++mt)
            #pragma unroll
            for (int nt = 0; nt < 4; ++nt)
                #pragma unroll
                for (int c = 0; c < 4; ++c) acc[mt][nt][c] = 0.f;

        #pragma unroll
        for (int s = 0; s < 8; ++s) {
            const uint32_t p0 = ((uint32_t)(8 * s + tq)) ^ mg;
            const uint32_t p1 = ((uint32_t)(8 * s + tq + 4)) ^ mg;

            uint32_t ahi[2][4], alo[2][4];
            #pragma unroll
            for (int mt = 0; mt < 2; ++mt) {
                const int ra = wr * 32 + mt * 16 + g;
                const float* Ra = As + ra * 128;
                const float* Rb = As + (ra + 8) * 128;
                float2 f0 = *reinterpret_cast<const float2*>(Ra + p0 * 2);
                float2 f1 = *reinterpret_cast<const float2*>(Rb + p0 * 2);
                float2 f2 = *reinterpret_cast<const float2*>(Ra + p1 * 2);
                float2 f3 = *reinterpret_cast<const float2*>(Rb + p1 * 2);
                uint32_t h0 = cvt_bf2(f0.x, f0.y);
                uint32_t h1 = cvt_bf2(f1.x, f1.y);
                uint32_t h2 = cvt_bf2(f2.x, f2.y);
                uint32_t h3 = cvt_bf2(f3.x, f3.y);
                ahi[mt][0] = h0; ahi[mt][1] = h1; ahi[mt][2] = h2; ahi[mt][3] = h3;
                alo[mt][0] = cvt_bf2(f0.x - __uint_as_float(h0 << 16),
                                     f0.y - __uint_as_float(h0 & 0xFFFF0000u));
                alo[mt][1] = cvt_bf2(f1.x - __uint_as_float(h1 << 16),
                                     f1.y - __uint_as_float(h1 & 0xFFFF0000u));
                alo[mt][2] = cvt_bf2(f2.x - __uint_as_float(h2 << 16),
                                     f2.y - __uint_as_float(h2 & 0xFFFF0000u));
                alo[mt][3] = cvt_bf2(f3.x - __uint_as_float(h3 << 16),
                                     f3.y - __uint_as_float(h3 & 0xFFFF0000u));
            }

            #pragma unroll
            for (int nt = 0; nt < 4; ++nt) {
                const int rb = wc * 32 + nt * 8 + g;
                const uint32_t* BH = reinterpret_cast<const uint32_t*>(smem + SMB_BHI + rb * 256);
                const uint32_t* BL = reinterpret_cast<const uint32_t*>(smem + SMB_BLO + rb * 256);
                uint32_t bh0 = BH[p0], bh1 = BH[p1];
                uint32_t bl0 = BL[p0], bl1 = BL[p1];
                #pragma unroll
                for (int mt = 0; mt < 2; ++mt) {
                    mma16816(acc[mt][nt], ahi[mt], bh0, bh1);
                    mma16816(acc[mt][nt], ahi[mt], bl0, bl1);
                    mma16816(acc[mt][nt], alo[mt], bh0, bh1);
                }
            }
        }

        // epilogue: * norm, store f32
        #pragma unroll
        for (int mt = 0; mt < 2; ++mt) {
            const int rA = row0 + wr * 32 + mt * 16 + g;
            const int rB = rA + 8;
            const bool okA = rA < N_NODES, okB = rB < N_NODES;
            const float sA = okA ? __ldg(norm + rA) : 0.f;
            const float sB = okB ? __ldg(norm + rB) : 0.f;
            #pragma unroll
            for (int nt = 0; nt < 4; ++nt) {
                const int col = wc * 32 + nt * 8 + tq * 2;
                if (okA) {
                    float2 v = make_float2(acc[mt][nt][0] * sA, acc[mt][nt][1] * sA);
                    *reinterpret_cast<float2*>(out + (size_t)rA * HD + col) = v;
                }
                if (okB) {
                    float2 v = make_float2(acc[mt][nt][2] * sB, acc[mt][nt][3] * sB);
                    *reinterpret_cast<float2*>(out + (size_t)rB * HD + col) = v;
                }
            }
        }
        __syncthreads();   // protect A buffer before restage at i+2
    }
}

// ================= CSR build =================

__global__ void hist_kernel(const int* __restrict__ dst, int* __restrict__ deg) {
    int e = blockIdx.x * 256 + threadIdx.x;
    if (e < N_EDGES) atomicAdd(&deg[dst[e]], 1);
}

__global__ void scan_block_kernel(const int* __restrict__ deg,
                                  int* __restrict__ rowptr,
                                  int* __restrict__ partials) {
    __shared__ int wsum[8];
    const int t = threadIdx.x;
    const int base = blockIdx.x * SCAN_CHUNK + t * 4;
    int v[4];
    #pragma unroll
    for (int j = 0; j < 4; ++j) {
        int i = base + j;
        v[j] = (i < N_NODES) ? deg[i] : 0;
    }
    int s = v[0] + v[1] + v[2] + v[3];
    const int lane = t & 31, wid = t >> 5;
    int x = s;
    #pragma unroll
    for (int o = 1; o < 32; o <<= 1) {
        int y = __shfl_up_sync(~0u, x, o);
        if (lane >= o) x += y;
    }
    if (lane == 31) wsum[wid] = x;
    __syncthreads();
    if (wid == 0) {
        int ws = (lane < 8) ? wsum[lane] : 0;
        #pragma unroll
        for (int o = 1; o < 8; o <<= 1) {
            int y = __shfl_up_sync(~0u, ws, o);
            if (lane >= o) ws += y;
        }
        if (lane < 8) wsum[lane] = ws;
    }
    __syncthreads();
    int run = (x - s) + (wid > 0 ? wsum[wid - 1] : 0);
    #pragma unroll
    for (int j = 0; j < 4; ++j) {
        int i = base + j;
        if (i < N_NODES) rowptr[i] = run;
        run += v[j];
    }
    if (t == 0) partials[blockIdx.x] = wsum[7];
}

__global__ void scan_partials_kernel(int* __restrict__ partials) {
    __shared__ int wsum[4];
    const int t = threadIdx.x;
    int v = (t < NBLK) ? partials[t] : 0;
    const int lane = t & 31, wid = t >> 5;
    int x = v;
    #pragma unroll
    for (int o = 1; o < 32; o <<= 1) {
        int y = __shfl_up_sync(~0u, x, o);
        if (lane >= o) x += y;
    }
    if (lane == 31) wsum[wid] = x;
    __syncthreads();
    if (t == 0) {
        int a = 0;
        #pragma unroll
        for (int w = 0; w < 4; ++w) { int s2 = wsum[w]; wsum[w] = a; a += s2; }
    }
    __syncthreads();
    int excl = (x - v) + wsum[wid];
    if (t < NBLK) partials[t] = excl;
}

__global__ void scan_add_kernel(int* __restrict__ rowptr,
                                const int* __restrict__ partials,
                                int* __restrict__ cursor) {
    int i = blockIdx.x * 256 + threadIdx.x;
    if (i < N_NODES) {
        int r = rowptr[i] + partials[i >> 10];
        rowptr[i] = r;
        cursor[i] = r;
    }
}

__global__ void permute_kernel(const int* __restrict__ src,
                               const int* __restrict__ dst,
                               int* __restrict__ cursor,
                               int* __restrict__ ssrc) {
    int e = blockIdx.x * 256 + threadIdx.x;
    if (e < N_EDGES) {
        int d = dst[e];
        int pos = atomicAdd(&cursor[d], 1);
        ssrc[pos] = src[e];
    }
}

// ================= load-balanced gather + fused epilogue =================
#define GATHER_BLOCKS 512
__global__ void gather_kernel(const float* __restrict__ M,
                              const int* __restrict__ rowptr,
                              const int* __restrict__ deg,
                              const int* __restrict__ ssrc,
                              const float* __restrict__ norm,
                              const float* __restrict__ b,
                              float* __restrict__ out) {
    const int gw = blockIdx.x * 8 + (threadIdx.x >> 5);
    const int lane = threadIdx.x & 31;
    const int nwarps = GATHER_BLOCKS * 8;
    const float4 bb = __ldg(reinterpret_cast<const float4*>(b) + lane);

    for (int node = gw; node < N_NODES; node += nwarps) {
        const int start = __ldg(rowptr + node);
        const int d = __ldg(deg + node);
        float4 acc = make_float4(0.f, 0.f, 0.f, 0.f);
        #pragma unroll 4
        for (int j = 0; j < d; ++j) {
            int s = __ldg(ssrc + start + j);
            float4 v = __ldg(reinterpret_cast<const float4*>(M + (size_t)s * HD) + lane);
            acc.x += v.x; acc.y += v.y; acc.z += v.z; acc.w += v.w;
        }
        const float sc = __ldg(norm + node);
        float4 n;
        n.x = leaky(acc.x * sc + bb.x);
        n.y = leaky(acc.y * sc + bb.y);
        n.z = leaky(acc.z * sc + bb.z);
        n.w = leaky(acc.w * sc + bb.w);
        reinterpret_cast<float4*>(out + (size_t)node * HD)[lane] = n;
    }
}

extern "C" void kernel_launch(void* const* d_in, const int* in_sizes, int n_in,
                              void* d_out, int out_size) {
    const int*   node_id = (const int*)d_in[0];
    const int*   src     = (const int*)d_in[1];
    const int*   dst     = (const int*)d_in[2];
    const float* norm    = (const float*)d_in[3];
    const float* embed   = (const float*)d_in[4];
    const float* W1      = (const float*)d_in[5];
    const float* b1      = (const float*)d_in[6];
    const float* W2      = (const float*)d_in[7];
    const float* b2      = (const float*)d_in[8];
    float* out = (float*)d_out;

    void *pM, *pH, *pDeg, *pRow, *pCur, *pSS, *pPart, *pWh, *pWl;
    cudaGetSymbolAddress(&pM, g_M);
    cudaGetSymbolAddress(&pH, g_H);
    cudaGetSymbolAddress(&pDeg, g_deg);
    cudaGetSymbolAddress(&pRow, g_rowptr);
    cudaGetSymbolAddress(&pCur, g_cursor);
    cudaGetSymbolAddress(&pSS, g_ssrc);
    cudaGetSymbolAddress(&pPart, g_partials);
    cudaGetSymbolAddress(&pWh, g_WT_hi);
    cudaGetSymbolAddress(&pWl, g_WT_lo);
    float* M = (float*)pM;
    float* H = (float*)pH;
    int *deg = (int*)pDeg, *rowptr = (int*)pRow, *cursor = (int*)pCur;
    int *ssrc = (int*)pSS, *partials = (int*)pPart;
    __nv_bfloat16 *wt_hi = (__nv_bfloat16*)pWh, *wt_lo = (__nv_bfloat16*)pWl;

    cudaFuncSetAttribute(hmma_gemm_kernel,
                         cudaFuncAttributeMaxDynamicSharedMemorySize, SM_TOTAL);

    const int edge_grid = (N_EDGES + 255) / 256;
    const int node_grid = (N_NODES + 255) / 256;
    const int wt_grid   = (HD * HD + 255) / 256;

    // Launch order arranged so the GEMM is the 4th non-memset kernel (ncu window).
    // CSR front-half (independent of GEMM):
    cudaMemsetAsync(deg, 0, N_NODES * sizeof(int));
    hist_kernel<<<edge_grid, 256>>>(dst, deg);
    scan_block_kernel<<<NBLK, 256>>>(deg, rowptr, partials);

    // ---- Layer 1 GEMM (embedding gather fused) ----
    prep_wt_kernel<<<wt_grid, 256>>>(W1, wt_hi, wt_lo);
    hmma_gemm_kernel<<<GEMM_CTAS, 512, SM_TOTAL>>>(embed, node_id, wt_hi, wt_lo, norm, M);

    // CSR back-half:
    scan_partials_kernel<<<1, 128>>>(partials);
    scan_add_kernel<<<node_grid, 256>>>(rowptr, partials, cursor);
    permute_kernel<<<edge_grid, 256>>>(src, dst, cursor, ssrc);

    gather_kernel<<<GATHER_BLOCKS, 256>>>(M, rowptr, deg, ssrc, norm, b1, H);

    // ---- Layer 2 ----
    prep_wt_kernel<<<wt_grid, 256>>>(W2, wt_hi, wt_lo);
    hmma_gemm_kernel<<<GEMM_CTAS, 512, SM_TOTAL>>>(H, nullptr, wt_hi, wt_lo, norm, M);
    gather_kernel<<<GATHER_BLOCKS, 256>>>(M, rowptr, deg, ssrc, norm, b2, out);
}

// round 7
// speedup vs baseline: 1.1674x; 1.0326x over previous
#include <cuda_runtime.h>
#include <cuda_bf16.h>
#include <cstdint>
#include <cstddef>

#define N_NODES 100000
#define N_EDGES 600000
#define HD 128
#define TILE_M 128
#define GTILES ((N_NODES + TILE_M - 1) / TILE_M)   // 782
#define GEMM_CTAS 148
#define SCAN_CHUNK 1024
#define NBLK ((N_NODES + SCAN_CHUNK - 1) / SCAN_CHUNK)   // 98

// ---- scratch (allocation-free) ----
__device__ float g_M[(size_t)N_NODES * HD];
__device__ float g_H[(size_t)N_NODES * HD];
__device__ int   g_deg[N_NODES];
__device__ int   g_rowptr[N_NODES];
__device__ int   g_cursor[N_NODES];
__device__ int   g_ssrc[N_EDGES];
__device__ int   g_partials[NBLK];
__device__ __nv_bfloat16 g_WT_hi[HD * HD];   // WT[n][k] = W[k][n], hi split
__device__ __nv_bfloat16 g_WT_lo[HD * HD];   // residual split

__device__ __forceinline__ float leaky(float x) { return x > 0.f ? x : 0.2f * x; }

__device__ __forceinline__ uint32_t smem_u32(const void* p) {
    uint32_t a;
    asm("{ .reg .u64 t; cvta.to.shared.u64 t, %1; cvt.u32.u64 %0, t; }" : "=r"(a) : "l"(p));
    return a;
}
// pack two f32 -> bf16x2: lo_half holds first arg
__device__ __forceinline__ uint32_t cvt_bf2(float lo_half, float hi_half) {
    uint32_t r;
    asm("cvt.rn.bf16x2.f32 %0, %1, %2;" : "=r"(r) : "f"(hi_half), "f"(lo_half));
    return r;
}
// D += A * B  (m16n8k16 bf16->f32) — plain sm_80 PTX
__device__ __forceinline__ void mma16816(float* d, const uint32_t* a, uint32_t b0, uint32_t b1) {
    asm volatile(
        "mma.sync.aligned.m16n8k16.row.col.f32.bf16.bf16.f32 "
        "{%0,%1,%2,%3}, {%4,%5,%6,%7}, {%8,%9}, {%0,%1,%2,%3};"
        : "+f"(d[0]), "+f"(d[1]), "+f"(d[2]), "+f"(d[3])
        : "r"(a[0]), "r"(a[1]), "r"(a[2]), "r"(a[3]), "r"(b0), "r"(b1));
}
__device__ __forceinline__ void ldsm4(uint32_t* r, uint32_t addr) {
    asm volatile("ldmatrix.sync.aligned.m8n8.x4.shared.b16 {%0,%1,%2,%3}, [%4];"
                 : "=r"(r[0]), "=r"(r[1]), "=r"(r[2]), "=r"(r[3]) : "r"(addr));
}
__device__ __forceinline__ void cp_async16(uint32_t daddr, const void* gaddr, int src_bytes) {
    asm volatile("cp.async.cg.shared.global [%0], [%1], 16, %2;"
                 :: "r"(daddr), "l"(gaddr), "r"(src_bytes) : "memory");
}
#define CP_COMMIT() asm volatile("cp.async.commit_group;" ::: "memory")
#define CP_WAIT0()  asm volatile("cp.async.wait_group 0;" ::: "memory")

// ================= W^T hi/lo prep =================
__global__ void prep_wt_kernel(const float* __restrict__ W,
                               __nv_bfloat16* __restrict__ wt_hi,
                               __nv_bfloat16* __restrict__ wt_lo) {
    int idx = blockIdx.x * 256 + threadIdx.x;
    if (idx >= HD * HD) return;
    int n = idx >> 7, k = idx & 127;
    float x = W[k * HD + n];
    __nv_bfloat16 h = __float2bfloat16_rn(x);
    float r = x - __bfloat162float(h);
    wt_hi[idx] = h;
    wt_lo[idx] = __float2bfloat16_rn(r);
}

// ================= persistent pipelined HMMA GEMM (ldmatrix + pre-split A) ===
// out[row,:] = (X[gather(row),:] @ W) * norm[row], split-bf16 3-product
// SMEM: Bhi 32K | Blo 32K | Ahi 32K | Alo 32K | A-f32 stage 64K = 192KB
#define SMB_BHI 0
#define SMB_BLO 32768
#define SMB_AHI 65536
#define SMB_ALO 98304
#define SMB_F32 131072
#define SM_TOTAL 196608

__global__ __launch_bounds__(512, 1)
void hmma_gemm_kernel(const float* __restrict__ X,
                      const int* __restrict__ idx,    // nullable
                      const __nv_bfloat16* __restrict__ wt_hi,
                      const __nv_bfloat16* __restrict__ wt_lo,
                      const float* __restrict__ norm,
                      float* __restrict__ out) {
    extern __shared__ char smem[];
    const uint32_t sb = smem_u32(smem);
    const int t = threadIdx.x;

    // ---- load B hi/lo once: chunk c of row r stored at chunk c^(r&7) ----
    {
        const int r = t >> 2;
        const uint32_t m = (r & 7) << 2;   // granule-index xor mask (bits 2..4)
        const uint4* bh = reinterpret_cast<const uint4*>(wt_hi + r * HD);
        const uint4* bl = reinterpret_cast<const uint4*>(wt_lo + r * HD);
        #pragma unroll
        for (int j = 0; j < 4; ++j) {
            int u = (t & 3) * 4 + j;
            uint32_t q = (uint32_t)(4 * u) ^ m;
            *reinterpret_cast<uint4*>(smem + SMB_BHI + r * 256 + q * 4) = __ldg(bh + u);
            *reinterpret_cast<uint4*>(smem + SMB_BLO + r * 256 + q * 4) = __ldg(bl + u);
        }
    }

    // tiles owned by this CTA
    int tiles[8];
    int ntl = 0;
    for (int tile = blockIdx.x; tile < GTILES; tile += GEMM_CTAS) tiles[ntl++] = tile;

    // ---- stage A tile (f32, swizzled) into SMB_F32 via cp.async ----
    const int sr_ = t >> 2;
    const uint32_t sm_ = (sr_ & 7) << 2;
    auto stage = [&](int tile) {
        const int row = tile * TILE_M + sr_;
        const uint32_t abase = sb + SMB_F32 + sr_ * 512;
        int srow = 0, vbytes = 0;
        if (row < N_NODES) { srow = idx ? __ldg(idx + row) : row; vbytes = 16; }
        const float4* g = reinterpret_cast<const float4*>(X + (size_t)srow * HD);
        #pragma unroll
        for (int j = 0; j < 8; ++j) {
            int c4 = (t & 3) * 8 + j;
            uint32_t gq = (uint32_t)(2 * c4) ^ sm_;
            cp_async16(abase + gq * 8, g + c4, vbytes);
        }
    };
    // ---- convert staged f32 tile -> Ahi/Alo bf16 (same swizzle index space) ----
    auto convert = [&]() {
        const float* Asrc = reinterpret_cast<const float*>(smem + SMB_F32) + sr_ * 128;
        uint32_t* Dhi = reinterpret_cast<uint32_t*>(smem + SMB_AHI) + sr_ * 64;
        uint32_t* Dlo = reinterpret_cast<uint32_t*>(smem + SMB_ALO) + sr_ * 64;
        #pragma unroll
        for (int j = 0; j < 8; ++j) {
            int c4 = (t & 3) * 8 + j;
            uint32_t gq = (uint32_t)(2 * c4) ^ sm_;
            float4 f = *reinterpret_cast<const float4*>(Asrc + gq * 2);
            uint32_t h0 = cvt_bf2(f.x, f.y);
            uint32_t h1 = cvt_bf2(f.z, f.w);
            uint32_t l0 = cvt_bf2(f.x - __uint_as_float(h0 << 16),
                                  f.y - __uint_as_float(h0 & 0xFFFF0000u));
            uint32_t l1 = cvt_bf2(f.z - __uint_as_float(h1 << 16),
                                  f.w - __uint_as_float(h1 & 0xFFFF0000u));
            Dhi[gq] = h0; Dhi[gq + 1] = h1;
            Dlo[gq] = l0; Dlo[gq + 1] = l1;
        }
    };

    // ---- warp tiling: 16 warps = 4x4; warp tile 32x32 ----
    const int lane = t & 31, wid = t >> 5;
    const int wr = wid >> 2, wc = wid & 3;
    const int g = lane >> 2, tq = lane & 3;

    // ldmatrix per-lane row assignment: sub 0..3 -> (row half, k chunk)
    const int sub = lane >> 3, subrow = lane & 7;
    const int cs = sub >> 1;            // k-chunk select within k16
    const int s8 = (sub & 1) * 8;       // row half
    const int rA0 = wr * 32 + s8 + subrow;
    const int rA1 = rA0 + 16;
    const int rB0 = wc * 32 + s8 + subrow;
    const int rB1 = rB0 + 16;
    const uint32_t baA0 = rA0 * 256, r7A0 = rA0 & 7;
    const uint32_t baA1 = rA1 * 256, r7A1 = rA1 & 7;
    const uint32_t baB0 = rB0 * 256, r7B0 = rB0 & 7;
    const uint32_t baB1 = rB1 * 256, r7B1 = rB1 & 7;
    const uint32_t aHI = sb + SMB_AHI, aLO = sb + SMB_ALO;
    const uint32_t bHI = sb + SMB_BHI, bLO = sb + SMB_BLO;

    // ---- prologue ----
    stage(tiles[0]); CP_COMMIT();
    CP_WAIT0(); __syncthreads();
    convert(); __syncthreads();
    if (ntl > 1) { stage(tiles[1]); CP_COMMIT(); }

    for (int i = 0; i < ntl; ++i) {
        const int row0 = tiles[i] * TILE_M;

        float acc[2][4][4];
        #pragma unroll
        for (int mt = 0; mt < 2; ++mt)
            #pragma unroll
            for (int nt = 0; nt < 4; ++nt)
                #pragma unroll
                for (int c = 0; c < 4; ++c) acc[mt][nt][c] = 0.f;

        #pragma unroll
        for (int s = 0; s < 8; ++s) {
            const uint32_t ck = (uint32_t)(2 * s + cs);
            const uint32_t oA0 = baA0 + ((ck ^ r7A0) << 4);
            const uint32_t oA1 = baA1 + ((ck ^ r7A1) << 4);
            const uint32_t oB0 = baB0 + ((ck ^ r7B0) << 4);
            const uint32_t oB1 = baB1 + ((ck ^ r7B1) << 4);

            uint32_t ah0[4], al0[4], ah1[4], al1[4];
            uint32_t bh0[4], bl0[4], bh1[4], bl1[4];
            ldsm4(ah0, aHI + oA0); ldsm4(al0, aLO + oA0);
            ldsm4(ah1, aHI + oA1); ldsm4(al1, aLO + oA1);
            ldsm4(bh0, bHI + oB0); ldsm4(bl0, bLO + oB0);
            ldsm4(bh1, bHI + oB1); ldsm4(bl1, bLO + oB1);

            // b-fragment regs: {b0 of even nt, b0 of odd nt, b1 of even nt, b1 of odd nt}
            #pragma unroll
            for (int mt = 0; mt < 2; ++mt) {
                const uint32_t* ah = mt ? ah1 : ah0;
                const uint32_t* al = mt ? al1 : al0;
                mma16816(acc[mt][0], ah, bh0[0], bh0[2]);
                mma16816(acc[mt][0], ah, bl0[0], bl0[2]);
                mma16816(acc[mt][0], al, bh0[0], bh0[2]);
                mma16816(acc[mt][1], ah, bh0[1], bh0[3]);
                mma16816(acc[mt][1], ah, bl0[1], bl0[3]);
                mma16816(acc[mt][1], al, bh0[1], bh0[3]);
                mma16816(acc[mt][2], ah, bh1[0], bh1[2]);
                mma16816(acc[mt][2], ah, bl1[0], bl1[2]);
                mma16816(acc[mt][2], al, bh1[0], bh1[2]);
                mma16816(acc[mt][3], ah, bh1[1], bh1[3]);
                mma16816(acc[mt][3], ah, bl1[1], bl1[3]);
                mma16816(acc[mt][3], al, bh1[1], bh1[3]);
            }
        }

        // ---- epilogue: * norm, store f32 ----
        #pragma unroll
        for (int mt = 0; mt < 2; ++mt) {
            const int rA = row0 + wr * 32 + mt * 16 + g;
            const int rB = rA + 8;
            const bool okA = rA < N_NODES, okB = rB < N_NODES;
            const float sA = okA ? __ldg(norm + rA) : 0.f;
            const float sB = okB ? __ldg(norm + rB) : 0.f;
            #pragma unroll
            for (int nt = 0; nt < 4; ++nt) {
                const int col = wc * 32 + nt * 8 + tq * 2;
                if (okA) {
                    float2 v = make_float2(acc[mt][nt][0] * sA, acc[mt][nt][1] * sA);
                    *reinterpret_cast<float2*>(out + (size_t)rA * HD + col) = v;
                }
                if (okB) {
                    float2 v = make_float2(acc[mt][nt][2] * sB, acc[mt][nt][3] * sB);
                    *reinterpret_cast<float2*>(out + (size_t)rB * HD + col) = v;
                }
            }
        }

        if (i + 1 < ntl) {
            CP_WAIT0();          // tile i+1 staged
            __syncthreads();     // all warps done reading Ahi/Alo of tile i
            convert();           // f32 stage -> Ahi/Alo
            __syncthreads();
            if (i + 2 < ntl) { stage(tiles[i + 2]); CP_COMMIT(); }
        }
    }
}

// ================= CSR build =================

__global__ void hist_kernel(const int* __restrict__ dst, int* __restrict__ deg) {
    int e = blockIdx.x * 256 + threadIdx.x;
    if (e < N_EDGES) atomicAdd(&deg[dst[e]], 1);
}

__global__ void scan_block_kernel(const int* __restrict__ deg,
                                  int* __restrict__ rowptr,
                                  int* __restrict__ partials) {
    __shared__ int wsum[8];
    const int t = threadIdx.x;
    const int base = blockIdx.x * SCAN_CHUNK + t * 4;
    int v[4];
    #pragma unroll
    for (int j = 0; j < 4; ++j) {
        int i = base + j;
        v[j] = (i < N_NODES) ? deg[i] : 0;
    }
    int s = v[0] + v[1] + v[2] + v[3];
    const int lane = t & 31, wid = t >> 5;
    int x = s;
    #pragma unroll
    for (int o = 1; o < 32; o <<= 1) {
        int y = __shfl_up_sync(~0u, x, o);
        if (lane >= o) x += y;
    }
    if (lane == 31) wsum[wid] = x;
    __syncthreads();
    if (wid == 0) {
        int ws = (lane < 8) ? wsum[lane] : 0;
        #pragma unroll
        for (int o = 1; o < 8; o <<= 1) {
            int y = __shfl_up_sync(~0u, ws, o);
            if (lane >= o) ws += y;
        }
        if (lane < 8) wsum[lane] = ws;
    }
    __syncthreads();
    int run = (x - s) + (wid > 0 ? wsum[wid - 1] : 0);
    #pragma unroll
    for (int j = 0; j < 4; ++j) {
        int i = base + j;
        if (i < N_NODES) rowptr[i] = run;
        run += v[j];
    }
    if (t == 0) partials[blockIdx.x] = wsum[7];
}

__global__ void scan_partials_kernel(int* __restrict__ partials) {
    __shared__ int wsum[4];
    const int t = threadIdx.x;
    int v = (t < NBLK) ? partials[t] : 0;
    const int lane = t & 31, wid = t >> 5;
    int x = v;
    #pragma unroll
    for (int o = 1; o < 32; o <<= 1) {
        int y = __shfl_up_sync(~0u, x, o);
        if (lane >= o) x += y;
    }
    if (lane == 31) wsum[wid] = x;
    __syncthreads();
    if (t == 0) {
        int a = 0;
        #pragma unroll
        for (int w = 0; w < 4; ++w) { int s2 = wsum[w]; wsum[w] = a; a += s2; }
    }
    __syncthreads();
    int excl = (x - v) + wsum[wid];
    if (t < NBLK) partials[t] = excl;
}

__global__ void scan_add_kernel(int* __restrict__ rowptr,
                                const int* __restrict__ partials,
                                int* __restrict__ cursor) {
    int i = blockIdx.x * 256 + threadIdx.x;
    if (i < N_NODES) {
        int r = rowptr[i] + partials[i >> 10];
        rowptr[i] = r;
        cursor[i] = r;
    }
}

__global__ void permute_kernel(const int* __restrict__ src,
                               const int* __restrict__ dst,
                               int* __restrict__ cursor,
                               int* __restrict__ ssrc) {
    int e = blockIdx.x * 256 + threadIdx.x;
    if (e < N_EDGES) {
        int d = dst[e];
        int pos = atomicAdd(&cursor[d], 1);
        ssrc[pos] = src[e];
    }
}

// ================= load-balanced gather + fused epilogue (MLP-4) =================
#define GATHER_BLOCKS 512
__global__ void gather_kernel(const float* __restrict__ M,
                              const int* __restrict__ rowptr,
                              const int* __restrict__ deg,
                              const int* __restrict__ ssrc,
                              const float* __restrict__ norm,
                              const float* __restrict__ b,
                              float* __restrict__ out) {
    const int gw = blockIdx.x * 8 + (threadIdx.x >> 5);
    const int lane = threadIdx.x & 31;
    const int nwarps = GATHER_BLOCKS * 8;
    const float4 bb = __ldg(reinterpret_cast<const float4*>(b) + lane);

    for (int node = gw; node < N_NODES; node += nwarps) {
        const int start = __ldg(rowptr + node);
        const int d = __ldg(deg + node);
        float4 acc = make_float4(0.f, 0.f, 0.f, 0.f);
        int j = 0;
        for (; j + 4 <= d; j += 4) {
            int s0 = __ldg(ssrc + start + j + 0);
            int s1 = __ldg(ssrc + start + j + 1);
            int s2 = __ldg(ssrc + start + j + 2);
            int s3 = __ldg(ssrc + start + j + 3);
            float4 v0 = __ldg(reinterpret_cast<const float4*>(M + (size_t)s0 * HD) + lane);
            float4 v1 = __ldg(reinterpret_cast<const float4*>(M + (size_t)s1 * HD) + lane);
            float4 v2 = __ldg(reinterpret_cast<const float4*>(M + (size_t)s2 * HD) + lane);
            float4 v3 = __ldg(reinterpret_cast<const float4*>(M + (size_t)s3 * HD) + lane);
            acc.x += v0.x + v1.x + v2.x + v3.x;
            acc.y += v0.y + v1.y + v2.y + v3.y;
            acc.z += v0.z + v1.z + v2.z + v3.z;
            acc.w += v0.w + v1.w + v2.w + v3.w;
        }
        for (; j < d; ++j) {
            int s = __ldg(ssrc + start + j);
            float4 v = __ldg(reinterpret_cast<const float4*>(M + (size_t)s * HD) + lane);
            acc.x += v.x; acc.y += v.y; acc.z += v.z; acc.w += v.w;
        }
        const float sc = __ldg(norm + node);
        float4 n;
        n.x = leaky(acc.x * sc + bb.x);
        n.y = leaky(acc.y * sc + bb.y);
        n.z = leaky(acc.z * sc + bb.z);
        n.w = leaky(acc.w * sc + bb.w);
        reinterpret_cast<float4*>(out + (size_t)node * HD)[lane] = n;
    }
}

extern "C" void kernel_launch(void* const* d_in, const int* in_sizes, int n_in,
                              void* d_out, int out_size) {
    const int*   node_id = (const int*)d_in[0];
    const int*   src     = (const int*)d_in[1];
    const int*   dst     = (const int*)d_in[2];
    const float* norm    = (const float*)d_in[3];
    const float* embed   = (const float*)d_in[4];
    const float* W1      = (const float*)d_in[5];
    const float* b1      = (const float*)d_in[6];
    const float* W2      = (const float*)d_in[7];
    const float* b2      = (const float*)d_in[8];
    float* out = (float*)d_out;

    void *pM, *pH, *pDeg, *pRow, *pCur, *pSS, *pPart, *pWh, *pWl;
    cudaGetSymbolAddress(&pM, g_M);
    cudaGetSymbolAddress(&pH, g_H);
    cudaGetSymbolAddress(&pDeg, g_deg);
    cudaGetSymbolAddress(&pRow, g_rowptr);
    cudaGetSymbolAddress(&pCur, g_cursor);
    cudaGetSymbolAddress(&pSS, g_ssrc);
    cudaGetSymbolAddress(&pPart, g_partials);
    cudaGetSymbolAddress(&pWh, g_WT_hi);
    cudaGetSymbolAddress(&pWl, g_WT_lo);
    float* M = (float*)pM;
    float* H = (float*)pH;
    int *deg = (int*)pDeg, *rowptr = (int*)pRow, *cursor = (int*)pCur;
    int *ssrc = (int*)pSS, *partials = (int*)pPart;
    __nv_bfloat16 *wt_hi = (__nv_bfloat16*)pWh, *wt_lo = (__nv_bfloat16*)pWl;

    cudaFuncSetAttribute(hmma_gemm_kernel,
                         cudaFuncAttributeMaxDynamicSharedMemorySize, SM_TOTAL);

    const int edge_grid = (N_EDGES + 255) / 256;
    const int node_grid = (N_NODES + 255) / 256;
    const int wt_grid   = (HD * HD + 255) / 256;

    // Launch order keeps the GEMM as the 4th non-memset kernel (ncu window).
    cudaMemsetAsync(deg, 0, N_NODES * sizeof(int));
    hist_kernel<<<edge_grid, 256>>>(dst, deg);
    scan_block_kernel<<<NBLK, 256>>>(deg, rowptr, partials);

    // ---- Layer 1 GEMM (embedding gather fused) ----
    prep_wt_kernel<<<wt_grid, 256>>>(W1, wt_hi, wt_lo);
    hmma_gemm_kernel<<<GEMM_CTAS, 512, SM_TOTAL>>>(embed, node_id, wt_hi, wt_lo, norm, M);

    // CSR back-half:
    scan_partials_kernel<<<1, 128>>>(partials);
    scan_add_kernel<<<node_grid, 256>>>(rowptr, partials, cursor);
    permute_kernel<<<edge_grid, 256>>>(src, dst, cursor, ssrc);

    gather_kernel<<<GATHER_BLOCKS, 256>>>(M, rowptr, deg, ssrc, norm, b1, H);

    // ---- Layer 2 ----
    prep_wt_kernel<<<wt_grid, 256>>>(W2, wt_hi, wt_lo);
    hmma_gemm_kernel<<<GEMM_CTAS, 512, SM_TOTAL>>>(H, nullptr, wt_hi, wt_lo, norm, M);
    gather_kernel<<<GATHER_BLOCKS, 256>>>(M, rowptr, deg, ssrc, norm, b2, out);
}

// round 8
// speedup vs baseline: 1.1681x; 1.0005x over previous
#include <cuda_runtime.h>
#include <cuda_bf16.h>
#include <cstdint>
#include <cstddef>

#define N_NODES 100000
#define N_EDGES 600000
#define HD 128
#define TILE_M 128
#define GTILES ((N_NODES + TILE_M - 1) / TILE_M)   // 782
#define GEMM_CTAS 148
#define SCAN_CHUNK 1024
#define NBLK ((N_NODES + SCAN_CHUNK - 1) / SCAN_CHUNK)   // 98

// ---- scratch (allocation-free) ----
__device__ float g_M[(size_t)N_NODES * HD];
__device__ float g_H[(size_t)N_NODES * HD];
__device__ int   g_deg[N_NODES];
__device__ int   g_rowptr[N_NODES];
__device__ int   g_cursor[N_NODES];
__device__ int   g_ssrc[N_EDGES];
__device__ int   g_partials[NBLK];
__device__ __nv_bfloat16 g_W1hi[HD * HD];
__device__ __nv_bfloat16 g_W1lo[HD * HD];
__device__ __nv_bfloat16 g_W2hi[HD * HD];
__device__ __nv_bfloat16 g_W2lo[HD * HD];

__device__ __forceinline__ float leaky(float x) { return x > 0.f ? x : 0.2f * x; }

__device__ __forceinline__ uint32_t smem_u32(const void* p) {
    uint32_t a;
    asm("{ .reg .u64 t; cvta.to.shared.u64 t, %1; cvt.u32.u64 %0, t; }" : "=r"(a) : "l"(p));
    return a;
}
// pack two f32 -> bf16x2 (round-to-nearest), first arg in LOW half
__device__ __forceinline__ uint32_t cvt_bf2(float lo_half, float hi_half) {
    uint32_t r;
    asm("cvt.rn.bf16x2.f32 %0, %1, %2;" : "=r"(r) : "f"(hi_half), "f"(lo_half));
    return r;
}
// D += A * B  (m16n8k16 bf16->f32) — plain sm_80 PTX
__device__ __forceinline__ void mma16816(float* d, const uint32_t* a, uint32_t b0, uint32_t b1) {
    asm volatile(
        "mma.sync.aligned.m16n8k16.row.col.f32.bf16.bf16.f32 "
        "{%0,%1,%2,%3}, {%4,%5,%6,%7}, {%8,%9}, {%0,%1,%2,%3};"
        : "+f"(d[0]), "+f"(d[1]), "+f"(d[2]), "+f"(d[3])
        : "r"(a[0]), "r"(a[1]), "r"(a[2]), "r"(a[3]), "r"(b0), "r"(b1));
}
__device__ __forceinline__ void ldsm4(uint32_t* r, uint32_t addr) {
    asm volatile("ldmatrix.sync.aligned.m8n8.x4.shared.b16 {%0,%1,%2,%3}, [%4];"
                 : "=r"(r[0]), "=r"(r[1]), "=r"(r[2]), "=r"(r[3]) : "r"(addr));
}
__device__ __forceinline__ void cp_async16(uint32_t daddr, const void* gaddr, int src_bytes) {
    asm volatile("cp.async.cg.shared.global [%0], [%1], 16, %2;"
                 :: "r"(daddr), "l"(gaddr), "r"(src_bytes) : "memory");
}
#define CP_COMMIT() asm volatile("cp.async.commit_group;" ::: "memory")
#define CP_WAIT1()  asm volatile("cp.async.wait_group 1;" ::: "memory")
#define CP_WAIT0()  asm volatile("cp.async.wait_group 0;" ::: "memory")

// ================= W^T hi/lo prep (both layers in one launch) =================
__global__ void prep_wt_kernel(const float* __restrict__ W1,
                               const float* __restrict__ W2,
                               __nv_bfloat16* __restrict__ w1hi,
                               __nv_bfloat16* __restrict__ w1lo,
                               __nv_bfloat16* __restrict__ w2hi,
                               __nv_bfloat16* __restrict__ w2lo) {
    int gid = blockIdx.x * 256 + threadIdx.x;
    int which = gid >= HD * HD;
    int idx = gid - which * HD * HD;
    if (idx >= HD * HD) return;
    const float* W = which ? W2 : W1;
    __nv_bfloat16* whi = which ? w2hi : w1hi;
    __nv_bfloat16* wlo = which ? w2lo : w1lo;
    int n = idx >> 7, k = idx & 127;
    float x = W[k * HD + n];
    __nv_bfloat16 h = __float2bfloat16_rn(x);
    float r = x - __bfloat162float(h);
    whi[idx] = h;
    wlo[idx] = __float2bfloat16_rn(r);
}

// ================= persistent pipelined HMMA GEMM =================
// out[row,:] = (X[gather(row),:] @ W) * norm[row], split-bf16 3-product
// SMEM: Bhi 32K | Blo 32K | A-f32 stage0 64K | stage1 64K = 192KB
#define SMB_BHI 0
#define SMB_BLO 32768
#define SMB_A0  65536
#define SMB_A1  131072
#define SM_TOTAL 196608

__global__ __launch_bounds__(512, 1)
void hmma_gemm_kernel(const float* __restrict__ X,
                      const int* __restrict__ idx,    // nullable
                      const __nv_bfloat16* __restrict__ wt_hi,
                      const __nv_bfloat16* __restrict__ wt_lo,
                      const float* __restrict__ norm,
                      float* __restrict__ out) {
    extern __shared__ char smem[];
    const uint32_t sb = smem_u32(smem);
    const int t = threadIdx.x;

    // ---- load B hi/lo once: 16B chunk c of row r stored at chunk c^(r&7) ----
    {
        const int r = t >> 2;
        const uint32_t m = (r & 7) << 2;   // granule(u32)-index xor mask
        const uint4* bh = reinterpret_cast<const uint4*>(wt_hi + r * HD);
        const uint4* bl = reinterpret_cast<const uint4*>(wt_lo + r * HD);
        #pragma unroll
        for (int j = 0; j < 4; ++j) {
            int u = (t & 3) * 4 + j;
            uint32_t q = (uint32_t)(4 * u) ^ m;
            *reinterpret_cast<uint4*>(smem + SMB_BHI + r * 256 + q * 4) = __ldg(bh + u);
            *reinterpret_cast<uint4*>(smem + SMB_BLO + r * 256 + q * 4) = __ldg(bl + u);
        }
    }

    // tiles owned by this CTA
    int tiles[8];
    int ntl = 0;
    for (int tile = blockIdx.x; tile < GTILES; tile += GEMM_CTAS) tiles[ntl++] = tile;

    // ---- stage A tile (f32, swizzled float2 granules) via cp.async ----
    const int sr_ = t >> 2;
    const uint32_t sm_ = (sr_ & 7) << 2;
    auto stage = [&](int buf, int tile) {
        const int row = tile * TILE_M + sr_;
        const uint32_t abase = sb + (buf ? SMB_A1 : SMB_A0) + sr_ * 512;
        int srow = 0, vbytes = 0;
        if (row < N_NODES) { srow = idx ? __ldg(idx + row) : row; vbytes = 16; }
        const float4* g = reinterpret_cast<const float4*>(X + (size_t)srow * HD);
        #pragma unroll
        for (int j = 0; j < 8; ++j) {
            int c4 = (t & 3) * 8 + j;
            uint32_t gq = (uint32_t)(2 * c4) ^ sm_;
            cp_async16(abase + gq * 8, g + c4, vbytes);
        }
    };

    // ---- warp tiling: 16 warps = 4x4; warp tile 32x32 (mt=2, nt=4) ----
    const int lane = t & 31, wid = t >> 5;
    const int wr = wid >> 2, wc = wid & 3;
    const int g = lane >> 2, tq = lane & 3;
    const uint32_t mg = (uint32_t)(g << 2);

    // B ldmatrix lane mapping (validated round 7)
    const int sub = lane >> 3, subrow = lane & 7;
    const int cs = sub >> 1;
    const int s8 = (sub & 1) * 8;
    const int rB0 = wc * 32 + s8 + subrow;
    const int rB1 = rB0 + 16;
    const uint32_t baB0 = rB0 * 256, r7B0 = rB0 & 7;
    const uint32_t baB1 = rB1 * 256, r7B1 = rB1 & 7;
    const uint32_t bHI = sb + SMB_BHI, bLO = sb + SMB_BLO;

    stage(0, tiles[0]);
    CP_COMMIT();

    for (int i = 0; i < ntl; ++i) {
        if (i + 1 < ntl) { stage((i + 1) & 1, tiles[i + 1]); CP_COMMIT(); CP_WAIT1(); }
        else             { CP_WAIT0(); }
        __syncthreads();

        const float* As = reinterpret_cast<const float*>(smem + ((i & 1) ? SMB_A1 : SMB_A0));
        const int row0 = tiles[i] * TILE_M;

        // A row base pointers (rows ra, ra+8 per mt)
        const float* Ra0 = As + (wr * 32 + g) * 128;
        const float* Rb0 = Ra0 + 8 * 128;
        const float* Ra1 = Ra0 + 16 * 128;
        const float* Rb1 = Ra1 + 8 * 128;

        float acc[2][4][4];
        #pragma unroll
        for (int mt = 0; mt < 2; ++mt)
            #pragma unroll
            for (int nt = 0; nt < 4; ++nt)
                #pragma unroll
                for (int c = 0; c < 4; ++c) acc[mt][nt][c] = 0.f;

        float2 fbuf[2][8];
        // prologue A-fragment load for s=0
        {
            uint32_t p0 = ((uint32_t)tq) ^ mg;
            uint32_t p1 = p0 ^ 4u;
            fbuf[0][0] = *reinterpret_cast<const float2*>(Ra0 + p0 * 2);
            fbuf[0][1] = *reinterpret_cast<const float2*>(Rb0 + p0 * 2);
            fbuf[0][2] = *reinterpret_cast<const float2*>(Ra0 + p1 * 2);
            fbuf[0][3] = *reinterpret_cast<const float2*>(Rb0 + p1 * 2);
            fbuf[0][4] = *reinterpret_cast<const float2*>(Ra1 + p0 * 2);
            fbuf[0][5] = *reinterpret_cast<const float2*>(Rb1 + p0 * 2);
            fbuf[0][6] = *reinterpret_cast<const float2*>(Ra1 + p1 * 2);
            fbuf[0][7] = *reinterpret_cast<const float2*>(Rb1 + p1 * 2);
        }

        #pragma unroll
        for (int s = 0; s < 8; ++s) {
            // B fragments via ldmatrix (issue early)
            const uint32_t ck = (uint32_t)(2 * s + cs);
            const uint32_t oB0 = baB0 + ((ck ^ r7B0) << 4);
            const uint32_t oB1 = baB1 + ((ck ^ r7B1) << 4);
            uint32_t bh0[4], bl0[4], bh1[4], bl1[4];
            ldsm4(bh0, bHI + oB0); ldsm4(bl0, bLO + oB0);
            ldsm4(bh1, bHI + oB1); ldsm4(bl1, bLO + oB1);

            // prefetch A f32 fragments for s+1
            if (s < 7) {
                uint32_t p0 = ((uint32_t)(8 * (s + 1) + tq)) ^ mg;
                uint32_t p1 = p0 ^ 4u;
                float2* fn = fbuf[(s + 1) & 1];
                fn[0] = *reinterpret_cast<const float2*>(Ra0 + p0 * 2);
                fn[1] = *reinterpret_cast<const float2*>(Rb0 + p0 * 2);
                fn[2] = *reinterpret_cast<const float2*>(Ra0 + p1 * 2);
                fn[3] = *reinterpret_cast<const float2*>(Rb0 + p1 * 2);
                fn[4] = *reinterpret_cast<const float2*>(Ra1 + p0 * 2);
                fn[5] = *reinterpret_cast<const float2*>(Rb1 + p0 * 2);
                fn[6] = *reinterpret_cast<const float2*>(Ra1 + p1 * 2);
                fn[7] = *reinterpret_cast<const float2*>(Rb1 + p1 * 2);
            }

            // convert current A fragments: hi via PRMT truncation, lo = exact residual
            const float2* f = fbuf[s & 1];
            uint32_t ahi[2][4], alo[2][4];
            #pragma unroll
            for (int mt = 0; mt < 2; ++mt)
                #pragma unroll
                for (int j = 0; j < 4; ++j) {
                    float2 v = f[mt * 4 + j];
                    uint32_t h = __byte_perm(__float_as_uint(v.x), __float_as_uint(v.y), 0x7632);
                    ahi[mt][j] = h;
                    alo[mt][j] = cvt_bf2(v.x - __uint_as_float(h << 16),
                                         v.y - __uint_as_float(h & 0xFFFF0000u));
                }

            #pragma unroll
            for (int mt = 0; mt < 2; ++mt) {
                const uint32_t* ah = ahi[mt];
                const uint32_t* al = alo[mt];
                mma16816(acc[mt][0], ah, bh0[0], bh0[2]);
                mma16816(acc[mt][0], ah, bl0[0], bl0[2]);
                mma16816(acc[mt][0], al, bh0[0], bh0[2]);
                mma16816(acc[mt][1], ah, bh0[1], bh0[3]);
                mma16816(acc[mt][1], ah, bl0[1], bl0[3]);
                mma16816(acc[mt][1], al, bh0[1], bh0[3]);
                mma16816(acc[mt][2], ah, bh1[0], bh1[2]);
                mma16816(acc[mt][2], ah, bl1[0], bl1[2]);
                mma16816(acc[mt][2], al, bh1[0], bh1[2]);
                mma16816(acc[mt][3], ah, bh1[1], bh1[3]);
                mma16816(acc[mt][3], ah, bl1[1], bl1[3]);
                mma16816(acc[mt][3], al, bh1[1], bh1[3]);
            }
        }

        // ---- epilogue: * norm, store f32 ----
        #pragma unroll
        for (int mt = 0; mt < 2; ++mt) {
            const int rA = row0 + wr * 32 + mt * 16 + g;
            const int rB = rA + 8;
            const bool okA = rA < N_NODES, okB = rB < N_NODES;
            const float sA = okA ? __ldg(norm + rA) : 0.f;
            const float sB = okB ? __ldg(norm + rB) : 0.f;
            #pragma unroll
            for (int nt = 0; nt < 4; ++nt) {
                const int col = wc * 32 + nt * 8 + tq * 2;
                if (okA) {
                    float2 v = make_float2(acc[mt][nt][0] * sA, acc[mt][nt][1] * sA);
                    *reinterpret_cast<float2*>(out + (size_t)rA * HD + col) = v;
                }
                if (okB) {
                    float2 v = make_float2(acc[mt][nt][2] * sB, acc[mt][nt][3] * sB);
                    *reinterpret_cast<float2*>(out + (size_t)rB * HD + col) = v;
                }
            }
        }
        __syncthreads();   // A buffer safe to restage
    }
}

// ================= CSR build =================

__global__ void hist_kernel(const int* __restrict__ dst, int* __restrict__ deg) {
    int e = blockIdx.x * 256 + threadIdx.x;
    if (e < N_EDGES) atomicAdd(&deg[dst[e]], 1);
}

__global__ void scan_block_kernel(const int* __restrict__ deg,
                                  int* __restrict__ rowptr,
                                  int* __restrict__ partials) {
    __shared__ int wsum[8];
    const int t = threadIdx.x;
    const int base = blockIdx.x * SCAN_CHUNK + t * 4;
    int v[4];
    #pragma unroll
    for (int j = 0; j < 4; ++j) {
        int i = base + j;
        v[j] = (i < N_NODES) ? deg[i] : 0;
    }
    int s = v[0] + v[1] + v[2] + v[3];
    const int lane = t & 31, wid = t >> 5;
    int x = s;
    #pragma unroll
    for (int o = 1; o < 32; o <<= 1) {
        int y = __shfl_up_sync(~0u, x, o);
        if (lane >= o) x += y;
    }
    if (lane == 31) wsum[wid] = x;
    __syncthreads();
    if (wid == 0) {
        int ws = (lane < 8) ? wsum[lane] : 0;
        #pragma unroll
        for (int o = 1; o < 8; o <<= 1) {
            int y = __shfl_up_sync(~0u, ws, o);
            if (lane >= o) ws += y;
        }
        if (lane < 8) wsum[lane] = ws;
    }
    __syncthreads();
    int run = (x - s) + (wid > 0 ? wsum[wid - 1] : 0);
    #pragma unroll
    for (int j = 0; j < 4; ++j) {
        int i = base + j;
        if (i < N_NODES) rowptr[i] = run;
        run += v[j];
    }
    if (t == 0) partials[blockIdx.x] = wsum[7];
}

__global__ void scan_partials_kernel(int* __restrict__ partials) {
    __shared__ int wsum[4];
    const int t = threadIdx.x;
    int v = (t < NBLK) ? partials[t] : 0;
    const int lane = t & 31, wid = t >> 5;
    int x = v;
    #pragma unroll
    for (int o = 1; o < 32; o <<= 1) {
        int y = __shfl_up_sync(~0u, x, o);
        if (lane >= o) x += y;
    }
    if (lane == 31) wsum[wid] = x;
    __syncthreads();
    if (t == 0) {
        int a = 0;
        #pragma unroll
        for (int w = 0; w < 4; ++w) { int s2 = wsum[w]; wsum[w] = a; a += s2; }
    }
    __syncthreads();
    int excl = (x - v) + wsum[wid];
    if (t < NBLK) partials[t] = excl;
}

__global__ void scan_add_kernel(int* __restrict__ rowptr,
                                const int* __restrict__ partials,
                                int* __restrict__ cursor) {
    int i = blockIdx.x * 256 + threadIdx.x;
    if (i < N_NODES) {
        int r = rowptr[i] + partials[i >> 10];
        rowptr[i] = r;
        cursor[i] = r;
    }
}

__global__ void permute_kernel(const int* __restrict__ src,
                               const int* __restrict__ dst,
                               int* __restrict__ cursor,
                               int* __restrict__ ssrc) {
    int e = blockIdx.x * 256 + threadIdx.x;
    if (e < N_EDGES) {
        int d = dst[e];
        int pos = atomicAdd(&cursor[d], 1);
        ssrc[pos] = src[e];
    }
}

// ================= load-balanced gather + fused epilogue (MLP-4) =================
#define GATHER_BLOCKS 512
__global__ void gather_kernel(const float* __restrict__ M,
                              const int* __restrict__ rowptr,
                              const int* __restrict__ deg,
                              const int* __restrict__ ssrc,
                              const float* __restrict__ norm,
                              const float* __restrict__ b,
                              float* __restrict__ out) {
    const int gw = blockIdx.x * 8 + (threadIdx.x >> 5);
    const int lane = threadIdx.x & 31;
    const int nwarps = GATHER_BLOCKS * 8;
    const float4 bb = __ldg(reinterpret_cast<const float4*>(b) + lane);

    for (int node = gw; node < N_NODES; node += nwarps) {
        const int start = __ldg(rowptr + node);
        const int d = __ldg(deg + node);
        float4 acc = make_float4(0.f, 0.f, 0.f, 0.f);
        int j = 0;
        for (; j + 4 <= d; j += 4) {
            int s0 = __ldg(ssrc + start + j + 0);
            int s1 = __ldg(ssrc + start + j + 1);
            int s2 = __ldg(ssrc + start + j + 2);
            int s3 = __ldg(ssrc + start + j + 3);
            float4 v0 = __ldg(reinterpret_cast<const float4*>(M + (size_t)s0 * HD) + lane);
            float4 v1 = __ldg(reinterpret_cast<const float4*>(M + (size_t)s1 * HD) + lane);
            float4 v2 = __ldg(reinterpret_cast<const float4*>(M + (size_t)s2 * HD) + lane);
            float4 v3 = __ldg(reinterpret_cast<const float4*>(M + (size_t)s3 * HD) + lane);
            acc.x += v0.x + v1.x + v2.x + v3.x;
            acc.y += v0.y + v1.y + v2.y + v3.y;
            acc.z += v0.z + v1.z + v2.z + v3.z;
            acc.w += v0.w + v1.w + v2.w + v3.w;
        }
        for (; j < d; ++j) {
            int s = __ldg(ssrc + start + j);
            float4 v = __ldg(reinterpret_cast<const float4*>(M + (size_t)s * HD) + lane);
            acc.x += v.x; acc.y += v.y; acc.z += v.z; acc.w += v.w;
        }
        const float sc = __ldg(norm + node);
        float4 n;
        n.x = leaky(acc.x * sc + bb.x);
        n.y = leaky(acc.y * sc + bb.y);
        n.z = leaky(acc.z * sc + bb.z);
        n.w = leaky(acc.w * sc + bb.w);
        reinterpret_cast<float4*>(out + (size_t)node * HD)[lane] = n;
    }
}

extern "C" void kernel_launch(void* const* d_in, const int* in_sizes, int n_in,
                              void* d_out, int out_size) {
    const int*   node_id = (const int*)d_in[0];
    const int*   src     = (const int*)d_in[1];
    const int*   dst     = (const int*)d_in[2];
    const float* norm    = (const float*)d_in[3];
    const float* embed   = (const float*)d_in[4];
    const float* W1      = (const float*)d_in[5];
    const float* b1      = (const float*)d_in[6];
    const float* W2      = (const float*)d_in[7];
    const float* b2      = (const float*)d_in[8];
    float* out = (float*)d_out;

    void *pM, *pH, *pDeg, *pRow, *pCur, *pSS, *pPart, *p1h, *p1l, *p2h, *p2l;
    cudaGetSymbolAddress(&pM, g_M);
    cudaGetSymbolAddress(&pH, g_H);
    cudaGetSymbolAddress(&pDeg, g_deg);
    cudaGetSymbolAddress(&pRow, g_rowptr);
    cudaGetSymbolAddress(&pCur, g_cursor);
    cudaGetSymbolAddress(&pSS, g_ssrc);
    cudaGetSymbolAddress(&pPart, g_partials);
    cudaGetSymbolAddress(&p1h, g_W1hi);
    cudaGetSymbolAddress(&p1l, g_W1lo);
    cudaGetSymbolAddress(&p2h, g_W2hi);
    cudaGetSymbolAddress(&p2l, g_W2lo);
    float* M = (float*)pM;
    float* H = (float*)pH;
    int *deg = (int*)pDeg, *rowptr = (int*)pRow, *cursor = (int*)pCur;
    int *ssrc = (int*)pSS, *partials = (int*)pPart;
    __nv_bfloat16 *w1hi = (__nv_bfloat16*)p1h, *w1lo = (__nv_bfloat16*)p1l;
    __nv_bfloat16 *w2hi = (__nv_bfloat16*)p2h, *w2lo = (__nv_bfloat16*)p2l;

    cudaFuncSetAttribute(hmma_gemm_kernel,
                         cudaFuncAttributeMaxDynamicSharedMemorySize, SM_TOTAL);

    const int edge_grid = (N_EDGES + 255) / 256;
    const int node_grid = (N_NODES + 255) / 256;
    const int wt_grid   = (2 * HD * HD + 255) / 256;

    // Launch order keeps the GEMM as the 4th non-memset kernel (ncu window).
    cudaMemsetAsync(deg, 0, N_NODES * sizeof(int));
    hist_kernel<<<edge_grid, 256>>>(dst, deg);
    scan_block_kernel<<<NBLK, 256>>>(deg, rowptr, partials);
    prep_wt_kernel<<<wt_grid, 256>>>(W1, W2, w1hi, w1lo, w2hi, w2lo);

    // ---- Layer 1 GEMM (embedding gather fused) ----
    hmma_gemm_kernel<<<GEMM_CTAS, 512, SM_TOTAL>>>(embed, node_id, w1hi, w1lo, norm, M);

    // CSR back-half:
    scan_partials_kernel<<<1, 128>>>(partials);
    scan_add_kernel<<<node_grid, 256>>>(rowptr, partials, cursor);
    permute_kernel<<<edge_grid, 256>>>(src, dst, cursor, ssrc);

    gather_kernel<<<GATHER_BLOCKS, 256>>>(M, rowptr, deg, ssrc, norm, b1, H);

    // ---- Layer 2 ----
    hmma_gemm_kernel<<<GEMM_CTAS, 512, SM_TOTAL>>>(H, nullptr, w2hi, w2lo, norm, M);
    gather_kernel<<<GATHER_BLOCKS, 256>>>(M, rowptr, deg, ssrc, norm, b2, out);
}

// round 9
// speedup vs baseline: 1.2847x; 1.0998x over previous
#include <cuda_runtime.h>
#include <cuda_bf16.h>
#include <cstdint>
#include <cstddef>

#define N_NODES 100000
#define N_EDGES 600000
#define HD 128
#define TILE_M 64
#define GTILES ((N_NODES + TILE_M - 1) / TILE_M)   // 1563
#define GEMM_CTAS 296
#define SCAN_CHUNK 1024
#define NBLK ((N_NODES + SCAN_CHUNK - 1) / SCAN_CHUNK)   // 98

// ---- scratch (allocation-free) ----
__device__ float g_M[(size_t)N_NODES * HD];
__device__ float g_H[(size_t)N_NODES * HD];
__device__ int   g_deg[N_NODES];
__device__ int   g_rowptr[N_NODES];
__device__ int   g_cursor[N_NODES];
__device__ int   g_ssrc[N_EDGES];
__device__ int   g_partials[NBLK];
__device__ __nv_bfloat16 g_W1hi[HD * HD];
__device__ __nv_bfloat16 g_W1lo[HD * HD];
__device__ __nv_bfloat16 g_W2hi[HD * HD];
__device__ __nv_bfloat16 g_W2lo[HD * HD];

__device__ __forceinline__ float leaky(float x) { return x > 0.f ? x : 0.2f * x; }

__device__ __forceinline__ uint32_t smem_u32(const void* p) {
    uint32_t a;
    asm("{ .reg .u64 t; cvta.to.shared.u64 t, %1; cvt.u32.u64 %0, t; }" : "=r"(a) : "l"(p));
    return a;
}
// pack two f32 -> bf16x2 (round-to-nearest), first arg in LOW half
__device__ __forceinline__ uint32_t cvt_bf2(float lo_half, float hi_half) {
    uint32_t r;
    asm("cvt.rn.bf16x2.f32 %0, %1, %2;" : "=r"(r) : "f"(hi_half), "f"(lo_half));
    return r;
}
// D += A * B  (m16n8k16 bf16->f32) — plain sm_80 PTX
__device__ __forceinline__ void mma16816(float* d, const uint32_t* a, uint32_t b0, uint32_t b1) {
    asm volatile(
        "mma.sync.aligned.m16n8k16.row.col.f32.bf16.bf16.f32 "
        "{%0,%1,%2,%3}, {%4,%5,%6,%7}, {%8,%9}, {%0,%1,%2,%3};"
        : "+f"(d[0]), "+f"(d[1]), "+f"(d[2]), "+f"(d[3])
        : "r"(a[0]), "r"(a[1]), "r"(a[2]), "r"(a[3]), "r"(b0), "r"(b1));
}
__device__ __forceinline__ void ldsm4(uint32_t* r, uint32_t addr) {
    asm volatile("ldmatrix.sync.aligned.m8n8.x4.shared.b16 {%0,%1,%2,%3}, [%4];"
                 : "=r"(r[0]), "=r"(r[1]), "=r"(r[2]), "=r"(r[3]) : "r"(addr));
}

// ================= W^T hi/lo prep (both layers, one launch) =================
__global__ void prep_wt_kernel(const float* __restrict__ W1,
                               const float* __restrict__ W2,
                               __nv_bfloat16* __restrict__ w1hi,
                               __nv_bfloat16* __restrict__ w1lo,
                               __nv_bfloat16* __restrict__ w2hi,
                               __nv_bfloat16* __restrict__ w2lo) {
    int gid = blockIdx.x * 256 + threadIdx.x;
    int which = gid >= HD * HD;
    int idx = gid - which * HD * HD;
    if (idx >= HD * HD) return;
    const float* W = which ? W2 : W1;
    __nv_bfloat16* whi = which ? w2hi : w1hi;
    __nv_bfloat16* wlo = which ? w2lo : w1lo;
    int n = idx >> 7, k = idx & 127;
    float x = W[k * HD + n];
    __nv_bfloat16 h = __float2bfloat16_rn(x);
    float r = x - __bfloat162float(h);
    whi[idx] = h;
    wlo[idx] = __float2bfloat16_rn(r);
}

// ================= persistent HMMA GEMM, 2 CTAs/SM =================
// out[row,:] = (X[gather(row),:] @ W) * norm[row], split-bf16 3-product.
// SMEM per CTA: Bhi 32K | Blo 32K | Ahi 16K | Alo 16K = 96KB
#define SMB_BHI 0
#define SMB_BLO 32768
#define SMB_AHI 65536
#define SMB_ALO 81920
#define SM_TOTAL 98304

__global__ __launch_bounds__(256, 2)
void hmma_gemm_kernel(const float* __restrict__ X,
                      const int* __restrict__ idx,    // nullable
                      const __nv_bfloat16* __restrict__ wt_hi,
                      const __nv_bfloat16* __restrict__ wt_lo,
                      const float* __restrict__ norm,
                      float* __restrict__ out) {
    extern __shared__ char smem[];
    const uint32_t sb = smem_u32(smem);
    const int t = threadIdx.x;

    // ---- load B hi/lo once: 16B chunk u of row r stored at chunk u^(r&7) ----
    {
        const int r = t >> 1;              // 0..127
        const int h = t & 1;
        const uint4* bh = reinterpret_cast<const uint4*>(wt_hi + r * HD);
        const uint4* bl = reinterpret_cast<const uint4*>(wt_lo + r * HD);
        #pragma unroll
        for (int j = 0; j < 8; ++j) {
            int u = h * 8 + j;             // chunk 0..15
            uint32_t q = (uint32_t)u ^ (uint32_t)(r & 7);
            *reinterpret_cast<uint4*>(smem + SMB_BHI + r * 256 + q * 16) = __ldg(bh + u);
            *reinterpret_cast<uint4*>(smem + SMB_BLO + r * 256 + q * 16) = __ldg(bl + u);
        }
    }

    // ---- warp tiling: 8 warps = 2 row-groups x 4 col-groups; warp tile 32x32 ----
    const int lane = t & 31, wid = t >> 5;
    const int wr = wid >> 2, wc = wid & 3;
    const int g = lane >> 2, tq = lane & 3;

    // ldmatrix lane mapping (validated rounds 7-8)
    const int sub = lane >> 3, subrow = lane & 7;
    const int cs = sub >> 1;            // k-chunk select
    const int s8 = (sub & 1) * 8;       // row half
    const int rB0 = wc * 32 + s8 + subrow;
    const int rB1 = rB0 + 16;
    const int rA0 = wr * 32 + s8 + subrow;   // mt0 m16 tile
    const int rA1 = rA0 + 16;                // mt1
    const uint32_t baB0 = rB0 * 256, r7B0 = rB0 & 7;
    const uint32_t baB1 = rB1 * 256, r7B1 = rB1 & 7;
    const uint32_t baA0 = rA0 * 256, r7A0 = rA0 & 7;
    const uint32_t baA1 = rA1 * 256, r7A1 = rA1 & 7;
    const uint32_t bHI = sb + SMB_BHI, bLO = sb + SMB_BLO;
    const uint32_t aHI = sb + SMB_AHI, aLO = sb + SMB_ALO;

    // staging coords: 4 threads per row, 8 float4 (32 cols) each
    const int sr_ = t >> 2;            // 0..63
    const int sq_ = t & 3;

    for (int tile = blockIdx.x; tile < GTILES; tile += GEMM_CTAS) {
        const int row0 = tile * TILE_M;

        __syncthreads();   // prior tile's readers done (also orders first tile after B load)

        // ---- stage A: LDG f32 -> split hi/lo bf16 -> STS (swizzled) ----
        {
            const int row = row0 + sr_;
            char* DH = smem + SMB_AHI + sr_ * 256;
            char* DL = smem + SMB_ALO + sr_ * 256;
            if (row < N_NODES) {
                const int srow = idx ? __ldg(idx + row) : row;
                const float4* gsrc = reinterpret_cast<const float4*>(X + (size_t)srow * HD);
                #pragma unroll
                for (int j = 0; j < 8; ++j) {
                    const int c4 = sq_ * 8 + j;          // float4 col index 0..31
                    float4 v = __ldg(gsrc + c4);
                    uint32_t h0 = __byte_perm(__float_as_uint(v.x), __float_as_uint(v.y), 0x7632);
                    uint32_t h1 = __byte_perm(__float_as_uint(v.z), __float_as_uint(v.w), 0x7632);
                    uint32_t l0 = cvt_bf2(v.x - __uint_as_float(h0 << 16),
                                          v.y - __uint_as_float(h0 & 0xFFFF0000u));
                    uint32_t l1 = cvt_bf2(v.z - __uint_as_float(h1 << 16),
                                          v.w - __uint_as_float(h1 & 0xFFFF0000u));
                    // granules 2*c4, 2*c4+1 -> chunk = c4>>1, offset = (2*c4)&3
                    uint32_t chunk = ((uint32_t)(c4 >> 1)) ^ (uint32_t)(sr_ & 7);
                    uint32_t off = chunk * 16 + ((uint32_t)(2 * c4) & 3) * 4;
                    *reinterpret_cast<uint2*>(DH + off) = make_uint2(h0, h1);
                    *reinterpret_cast<uint2*>(DL + off) = make_uint2(l0, l1);
                }
            } else {
                #pragma unroll
                for (int j = 0; j < 8; ++j) {
                    const int c4 = sq_ * 8 + j;
                    uint32_t chunk = ((uint32_t)(c4 >> 1)) ^ (uint32_t)(sr_ & 7);
                    uint32_t off = chunk * 16 + ((uint32_t)(2 * c4) & 3) * 4;
                    *reinterpret_cast<uint2*>(DH + off) = make_uint2(0u, 0u);
                    *reinterpret_cast<uint2*>(DL + off) = make_uint2(0u, 0u);
                }
            }
        }
        __syncthreads();

        // ---- compute: pure ldsm + mma ----
        float acc[2][4][4];
        #pragma unroll
        for (int mt = 0; mt < 2; ++mt)
            #pragma unroll
            for (int nt = 0; nt < 4; ++nt)
                #pragma unroll
                for (int c = 0; c < 4; ++c) acc[mt][nt][c] = 0.f;

        #pragma unroll
        for (int s = 0; s < 8; ++s) {
            const uint32_t ck = (uint32_t)(2 * s + cs);
            const uint32_t oA0 = baA0 + ((ck ^ r7A0) << 4);
            const uint32_t oA1 = baA1 + ((ck ^ r7A1) << 4);
            const uint32_t oB0 = baB0 + ((ck ^ r7B0) << 4);
            const uint32_t oB1 = baB1 + ((ck ^ r7B1) << 4);

            uint32_t ah0[4], al0[4], ah1[4], al1[4];
            uint32_t bh0[4], bl0[4], bh1[4], bl1[4];
            ldsm4(ah0, aHI + oA0); ldsm4(al0, aLO + oA0);
            ldsm4(ah1, aHI + oA1); ldsm4(al1, aLO + oA1);
            ldsm4(bh0, bHI + oB0); ldsm4(bl0, bLO + oB0);
            ldsm4(bh1, bHI + oB1); ldsm4(bl1, bLO + oB1);

            #pragma unroll
            for (int mt = 0; mt < 2; ++mt) {
                const uint32_t* ah = mt ? ah1 : ah0;
                const uint32_t* al = mt ? al1 : al0;
                mma16816(acc[mt][0], ah, bh0[0], bh0[2]);
                mma16816(acc[mt][0], ah, bl0[0], bl0[2]);
                mma16816(acc[mt][0], al, bh0[0], bh0[2]);
                mma16816(acc[mt][1], ah, bh0[1], bh0[3]);
                mma16816(acc[mt][1], ah, bl0[1], bl0[3]);
                mma16816(acc[mt][1], al, bh0[1], bh0[3]);
                mma16816(acc[mt][2], ah, bh1[0], bh1[2]);
                mma16816(acc[mt][2], ah, bl1[0], bl1[2]);
                mma16816(acc[mt][2], al, bh1[0], bh1[2]);
                mma16816(acc[mt][3], ah, bh1[1], bh1[3]);
                mma16816(acc[mt][3], ah, bl1[1], bl1[3]);
                mma16816(acc[mt][3], al, bh1[1], bh1[3]);
            }
        }

        // ---- epilogue: * norm, store f32 ----
        #pragma unroll
        for (int mt = 0; mt < 2; ++mt) {
            const int rA = row0 + wr * 32 + mt * 16 + g;
            const int rB = rA + 8;
            const bool okA = rA < N_NODES, okB = rB < N_NODES;
            const float sA = okA ? __ldg(norm + rA) : 0.f;
            const float sB = okB ? __ldg(norm + rB) : 0.f;
            #pragma unroll
            for (int nt = 0; nt < 4; ++nt) {
                const int col = wc * 32 + nt * 8 + tq * 2;
                if (okA) {
                    float2 v = make_float2(acc[mt][nt][0] * sA, acc[mt][nt][1] * sA);
                    *reinterpret_cast<float2*>(out + (size_t)rA * HD + col) = v;
                }
                if (okB) {
                    float2 v = make_float2(acc[mt][nt][2] * sB, acc[mt][nt][3] * sB);
                    *reinterpret_cast<float2*>(out + (size_t)rB * HD + col) = v;
                }
            }
        }
    }
}

// ================= CSR build =================

__global__ void hist_kernel(const int* __restrict__ dst, int* __restrict__ deg) {
    int e = blockIdx.x * 256 + threadIdx.x;
    if (e < N_EDGES) atomicAdd(&deg[dst[e]], 1);
}

__global__ void scan_block_kernel(const int* __restrict__ deg,
                                  int* __restrict__ rowptr,
                                  int* __restrict__ partials) {
    __shared__ int wsum[8];
    const int t = threadIdx.x;
    const int base = blockIdx.x * SCAN_CHUNK + t * 4;
    int v[4];
    #pragma unroll
    for (int j = 0; j < 4; ++j) {
        int i = base + j;
        v[j] = (i < N_NODES) ? deg[i] : 0;
    }
    int s = v[0] + v[1] + v[2] + v[3];
    const int lane = t & 31, wid = t >> 5;
    int x = s;
    #pragma unroll
    for (int o = 1; o < 32; o <<= 1) {
        int y = __shfl_up_sync(~0u, x, o);
        if (lane >= o) x += y;
    }
    if (lane == 31) wsum[wid] = x;
    __syncthreads();
    if (wid == 0) {
        int ws = (lane < 8) ? wsum[lane] : 0;
        #pragma unroll
        for (int o = 1; o < 8; o <<= 1) {
            int y = __shfl_up_sync(~0u, ws, o);
            if (lane >= o) ws += y;
        }
        if (lane < 8) wsum[lane] = ws;
    }
    __syncthreads();
    int run = (x - s) + (wid > 0 ? wsum[wid - 1] : 0);
    #pragma unroll
    for (int j = 0; j < 4; ++j) {
        int i = base + j;
        if (i < N_NODES) rowptr[i] = run;
        run += v[j];
    }
    if (t == 0) partials[blockIdx.x] = wsum[7];
}

__global__ void scan_partials_kernel(int* __restrict__ partials) {
    __shared__ int wsum[4];
    const int t = threadIdx.x;
    int v = (t < NBLK) ? partials[t] : 0;
    const int lane = t & 31, wid = t >> 5;
    int x = v;
    #pragma unroll
    for (int o = 1; o < 32; o <<= 1) {
        int y = __shfl_up_sync(~0u, x, o);
        if (lane >= o) x += y;
    }
    if (lane == 31) wsum[wid] = x;
    __syncthreads();
    if (t == 0) {
        int a = 0;
        #pragma unroll
        for (int w = 0; w < 4; ++w) { int s2 = wsum[w]; wsum[w] = a; a += s2; }
    }
    __syncthreads();
    int excl = (x - v) + wsum[wid];
    if (t < NBLK) partials[t] = excl;
}

__global__ void scan_add_kernel(int* __restrict__ rowptr,
                                const int* __restrict__ partials,
                                int* __restrict__ cursor) {
    int i = blockIdx.x * 256 + threadIdx.x;
    if (i < N_NODES) {
        int r = rowptr[i] + partials[i >> 10];
        rowptr[i] = r;
        cursor[i] = r;
    }
}

__global__ void permute_kernel(const int* __restrict__ src,
                               const int* __restrict__ dst,
                               int* __restrict__ cursor,
                               int* __restrict__ ssrc) {
    int e = blockIdx.x * 256 + threadIdx.x;
    if (e < N_EDGES) {
        int d = dst[e];
        int pos = atomicAdd(&cursor[d], 1);
        ssrc[pos] = src[e];
    }
}

// ================= load-balanced gather + fused epilogue (MLP-4) =================
#define GATHER_BLOCKS 512
__global__ void gather_kernel(const float* __restrict__ M,
                              const int* __restrict__ rowptr,
                              const int* __restrict__ deg,
                              const int* __restrict__ ssrc,
                              const float* __restrict__ norm,
                              const float* __restrict__ b,
                              float* __restrict__ out) {
    const int gw = blockIdx.x * 8 + (threadIdx.x >> 5);
    const int lane = threadIdx.x & 31;
    const int nwarps = GATHER_BLOCKS * 8;
    const float4 bb = __ldg(reinterpret_cast<const float4*>(b) + lane);

    for (int node = gw; node < N_NODES; node += nwarps) {
        const int start = __ldg(rowptr + node);
        const int d = __ldg(deg + node);
        float4 acc = make_float4(0.f, 0.f, 0.f, 0.f);
        int j = 0;
        for (; j + 4 <= d; j += 4) {
            int s0 = __ldg(ssrc + start + j + 0);
            int s1 = __ldg(ssrc + start + j + 1);
            int s2 = __ldg(ssrc + start + j + 2);
            int s3 = __ldg(ssrc + start + j + 3);
            float4 v0 = __ldg(reinterpret_cast<const float4*>(M + (size_t)s0 * HD) + lane);
            float4 v1 = __ldg(reinterpret_cast<const float4*>(M + (size_t)s1 * HD) + lane);
            float4 v2 = __ldg(reinterpret_cast<const float4*>(M + (size_t)s2 * HD) + lane);
            float4 v3 = __ldg(reinterpret_cast<const float4*>(M + (size_t)s3 * HD) + lane);
            acc.x += v0.x + v1.x + v2.x + v3.x;
            acc.y += v0.y + v1.y + v2.y + v3.y;
            acc.z += v0.z + v1.z + v2.z + v3.z;
            acc.w += v0.w + v1.w + v2.w + v3.w;
        }
        for (; j < d; ++j) {
            int s = __ldg(ssrc + start + j);
            float4 v = __ldg(reinterpret_cast<const float4*>(M + (size_t)s * HD) + lane);
            acc.x += v.x; acc.y += v.y; acc.z += v.z; acc.w += v.w;
        }
        const float sc = __ldg(norm + node);
        float4 n;
        n.x = leaky(acc.x * sc + bb.x);
        n.y = leaky(acc.y * sc + bb.y);
        n.z = leaky(acc.z * sc + bb.z);
        n.w = leaky(acc.w * sc + bb.w);
        reinterpret_cast<float4*>(out + (size_t)node * HD)[lane] = n;
    }
}

extern "C" void kernel_launch(void* const* d_in, const int* in_sizes, int n_in,
                              void* d_out, int out_size) {
    const int*   node_id = (const int*)d_in[0];
    const int*   src     = (const int*)d_in[1];
    const int*   dst     = (const int*)d_in[2];
    const float* norm    = (const float*)d_in[3];
    const float* embed   = (const float*)d_in[4];
    const float* W1      = (const float*)d_in[5];
    const float* b1      = (const float*)d_in[6];
    const float* W2      = (const float*)d_in[7];
    const float* b2      = (const float*)d_in[8];
    float* out = (float*)d_out;

    void *pM, *pH, *pDeg, *pRow, *pCur, *pSS, *pPart, *p1h, *p1l, *p2h, *p2l;
    cudaGetSymbolAddress(&pM, g_M);
    cudaGetSymbolAddress(&pH, g_H);
    cudaGetSymbolAddress(&pDeg, g_deg);
    cudaGetSymbolAddress(&pRow, g_rowptr);
    cudaGetSymbolAddress(&pCur, g_cursor);
    cudaGetSymbolAddress(&pSS, g_ssrc);
    cudaGetSymbolAddress(&pPart, g_partials);
    cudaGetSymbolAddress(&p1h, g_W1hi);
    cudaGetSymbolAddress(&p1l, g_W1lo);
    cudaGetSymbolAddress(&p2h, g_W2hi);
    cudaGetSymbolAddress(&p2l, g_W2lo);
    float* M = (float*)pM;
    float* H = (float*)pH;
    int *deg = (int*)pDeg, *rowptr = (int*)pRow, *cursor = (int*)pCur;
    int *ssrc = (int*)pSS, *partials = (int*)pPart;
    __nv_bfloat16 *w1hi = (__nv_bfloat16*)p1h, *w1lo = (__nv_bfloat16*)p1l;
    __nv_bfloat16 *w2hi = (__nv_bfloat16*)p2h, *w2lo = (__nv_bfloat16*)p2l;

    cudaFuncSetAttribute(hmma_gemm_kernel,
                         cudaFuncAttributeMaxDynamicSharedMemorySize, SM_TOTAL);

    const int edge_grid = (N_EDGES + 255) / 256;
    const int node_grid = (N_NODES + 255) / 256;
    const int wt_grid   = (2 * HD * HD + 255) / 256;

    // Launch order keeps the GEMM as the 4th non-memset kernel (ncu window).
    cudaMemsetAsync(deg, 0, N_NODES * sizeof(int));
    hist_kernel<<<edge_grid, 256>>>(dst, deg);
    scan_block_kernel<<<NBLK, 256>>>(deg, rowptr, partials);
    prep_wt_kernel<<<wt_grid, 256>>>(W1, W2, w1hi, w1lo, w2hi, w2lo);

    // ---- Layer 1 GEMM (embedding gather fused) ----
    hmma_gemm_kernel<<<GEMM_CTAS, 256, SM_TOTAL>>>(embed, node_id, w1hi, w1lo, norm, M);

    // CSR back-half:
    scan_partials_kernel<<<1, 128>>>(partials);
    scan_add_kernel<<<node_grid, 256>>>(rowptr, partials, cursor);
    permute_kernel<<<edge_grid, 256>>>(src, dst, cursor, ssrc);

    gather_kernel<<<GATHER_BLOCKS, 256>>>(M, rowptr, deg, ssrc, norm, b1, H);

    // ---- Layer 2 ----
    hmma_gemm_kernel<<<GEMM_CTAS, 256, SM_TOTAL>>>(H, nullptr, w2hi, w2lo, norm, M);
    gather_kernel<<<GATHER_BLOCKS, 256>>>(M, rowptr, deg, ssrc, norm, b2, out);
}